// round 7
// baseline (speedup 1.0000x reference)
#include <cuda_runtime.h>
#include <cstddef>

#define Nb 64
#define Ts 512
#define Dd 1024
#define Hh 1024
#define Gg 4096   // 4*Hh

typedef unsigned long long u64;

// Scratch: xW in (t, n, 4H) layout. 512 MB static device array (allowed; no allocs).
__device__ float g_xw[(size_t)Nb * Ts * Gg];
__device__ float g_hbuf[2][Nb * Hh];
__device__ float g_cbuf[Nb * Hh];

union F2U { u64 u; float2 f; };
union F4U { float4 f; u64 u[2]; };

#define FFMA2(d, a, b) asm("fma.rn.f32x2 %0, %1, %2, %0;" : "+l"(d) : "l"(a), "l"(b))
#define PACK2(d, s)    asm("mov.b64 %0, {%1, %1};" : "=l"(d) : "r"(s))

__device__ __forceinline__ void cp16(void* smem, const void* g) {
    unsigned saddr = (unsigned)__cvta_generic_to_shared(smem);
    asm volatile("cp.async.cg.shared.global [%0], [%1], 16;" :: "r"(saddr), "l"(g));
}
#define CP_COMMIT() asm volatile("cp.async.commit_group;")
#define CP_WAIT1()  asm volatile("cp.async.wait_group 1;")

// ===================================================================
// Kernel 1: xW[t*64+n][g] = bias[g] + sum_d x[n][t][d] * Wx[d][g]
// M=32768, N=4096, K=1024.  BM=128 BN=128 BK=16, 256 thr, 8x8/thread (f32x2).
// ===================================================================
__global__ __launch_bounds__(256) void xw_gemm(const float* __restrict__ x,
                                               const float* __restrict__ Wx,
                                               const float* __restrict__ bias) {
    __shared__ float As[2][128][20];   // [row][k], padded row=20 floats (16B-aligned chunks)
    __shared__ float Bs[2][16][128];   // [k][g]

    const int tid  = threadIdx.x;
    const int row0 = blockIdx.y * 128;
    const int col0 = blockIdx.x * 128;
    const int tx = tid & 15, ty = tid >> 4;

    // load maps
    const int arow = tid >> 2;          // 0..63 (and +64)
    const int ak   = (tid & 3) << 2;    // 0,4,8,12
    const int brow = tid >> 5;          // 0..7 (and +8)
    const int bcol = (tid & 31) << 2;   // 0..124

    F2U acc[8][4];
    #pragma unroll
    for (int i = 0; i < 8; i++)
        #pragma unroll
        for (int j = 0; j < 4; j++) acc[i][j].u = 0ull;

    // prefetch tile kt=0 into buf 0
    {
        #pragma unroll
        for (int rr = 0; rr < 2; rr++) {
            int r = arow + rr * 64;
            int m = row0 + r;
            int t = m >> 6, n = m & 63;
            cp16(&As[0][r][ak], x + ((size_t)n * Ts + t) * Dd + 0 + ak);
        }
        #pragma unroll
        for (int rr = 0; rr < 2; rr++) {
            int rb = brow + rr * 8;
            cp16(&Bs[0][rb][bcol], Wx + (size_t)(0 + rb) * Gg + col0 + bcol);
        }
        CP_COMMIT();
    }

    int buf = 0;
    for (int kt = 0; kt < Dd; kt += 16) {
        // prefetch next tile into other buffer
        if (kt + 16 < Dd) {
            #pragma unroll
            for (int rr = 0; rr < 2; rr++) {
                int r = arow + rr * 64;
                int m = row0 + r;
                int t = m >> 6, n = m & 63;
                cp16(&As[buf ^ 1][r][ak], x + ((size_t)n * Ts + t) * Dd + (kt + 16) + ak);
            }
            #pragma unroll
            for (int rr = 0; rr < 2; rr++) {
                int rb = brow + rr * 8;
                cp16(&Bs[buf ^ 1][rb][bcol], Wx + (size_t)(kt + 16 + rb) * Gg + col0 + bcol);
            }
        }
        CP_COMMIT();
        CP_WAIT1();
        __syncthreads();

        const float (*Asb)[20]  = As[buf];
        const float (*Bsb)[128] = Bs[buf];
        #pragma unroll
        for (int k = 0; k < 16; k++) {
            float a[8];
            #pragma unroll
            for (int i = 0; i < 8; i++) a[i] = Asb[ty * 8 + i][k];
            const u64* bp = (const u64*)&Bsb[k][tx * 8];
            u64 b2[4];
            b2[0] = bp[0]; b2[1] = bp[1]; b2[2] = bp[2]; b2[3] = bp[3];
            #pragma unroll
            for (int i = 0; i < 8; i++) {
                u64 a2; PACK2(a2, __float_as_uint(a[i]));
                FFMA2(acc[i][0].u, a2, b2[0]);
                FFMA2(acc[i][1].u, a2, b2[1]);
                FFMA2(acc[i][2].u, a2, b2[2]);
                FFMA2(acc[i][3].u, a2, b2[3]);
            }
        }
        __syncthreads();
        buf ^= 1;
    }

    // epilogue: add bias, store
    #pragma unroll
    for (int i = 0; i < 8; i++) {
        size_t m = (size_t)(row0 + ty * 8 + i);
        float* outp = g_xw + m * Gg + col0 + tx * 8;
        #pragma unroll
        for (int j = 0; j < 4; j++) {
            float2 v = acc[i][j].f;
            v.x += bias[col0 + tx * 8 + 2 * j + 0];
            v.y += bias[col0 + tx * 8 + 2 * j + 1];
            *(float2*)(outp + 2 * j) = v;
        }
    }
}

// ===================================================================
// Kernel 2: one LSTM step.
// Block jb owns hidden cols j0..j0+7 (all 4 gates, all 64 rows).
// A[n][gate*8+jj] = xw[t][n][gate*H + j0+jj] + sum_k h[n][k]*Wh[k][gate*H + j0+jj]
// 256 threads, each a 2x4 register tile (2 rows x 2 f32x2 col-pairs), K tiled by 32.
// ===================================================================
__global__ __launch_bounds__(256) void lstm_step(const float* __restrict__ Wh,
                                                 const float* __restrict__ h0,
                                                 float* __restrict__ out,
                                                 int t) {
    __shared__ float h_s[2][64][36];
    __shared__ float W_s[2][32][36];
    __shared__ float A_s[64][33];

    const int tid = threadIdx.x;
    const int j0  = blockIdx.x * 8;

    const float* h_in  = (t == 0) ? h0 : g_hbuf[t & 1];
    float*       h_out = g_hbuf[(t + 1) & 1];
    const float* xw    = g_xw + (size_t)t * Nb * Gg;

    // compute map: thread -> rows {n0, n0+1}, cols {c0..c0+3} of the 32 block cols
    const int cg = tid & 7;        const int c0 = cg * 4;
    const int rg = tid >> 3;       const int n0 = rg * 2;

    // load maps
    const int hn = tid >> 2;            // 0..63
    const int hk = (tid & 3) << 3;      // 0,8,16,24 (two 16B chunks each)
    const int wk = tid >> 3;            // 0..31
    const int wc = (tid & 7) << 2;      // 0,4,...,28
    const int wgate = wc >> 3;
    const int wjj   = wc & 7;
    const float* wgptr = Wh + (size_t)wgate * Hh + j0 + wjj;   // + (kt+wk)*Gg per tile

    F2U acc[2][2];
    acc[0][0].u = 0ull; acc[0][1].u = 0ull; acc[1][0].u = 0ull; acc[1][1].u = 0ull;

    // prefetch kt=0
    {
        cp16(&h_s[0][hn][hk + 0], h_in + hn * Hh + 0 + hk + 0);
        cp16(&h_s[0][hn][hk + 4], h_in + hn * Hh + 0 + hk + 4);
        cp16(&W_s[0][wk][wc],     wgptr + (size_t)(0 + wk) * Gg);
        CP_COMMIT();
    }

    int buf = 0;
    for (int kt = 0; kt < Hh; kt += 32) {
        if (kt + 32 < Hh) {
            cp16(&h_s[buf ^ 1][hn][hk + 0], h_in + hn * Hh + (kt + 32) + hk + 0);
            cp16(&h_s[buf ^ 1][hn][hk + 4], h_in + hn * Hh + (kt + 32) + hk + 4);
            cp16(&W_s[buf ^ 1][wk][wc],     wgptr + (size_t)(kt + 32 + wk) * Gg);
        }
        CP_COMMIT();
        CP_WAIT1();
        __syncthreads();

        const float (*hsb)[36] = h_s[buf];
        const float (*wsb)[36] = W_s[buf];
        #pragma unroll
        for (int kk = 0; kk < 32; kk += 2) {
            float2 aA = *(const float2*)&hsb[n0][kk];
            float2 aB = *(const float2*)&hsb[n0 + 1][kk];
            F4U w0, w1;
            w0.f = *(const float4*)&wsb[kk][c0];
            w1.f = *(const float4*)&wsb[kk + 1][c0];
            u64 d0, d1;
            PACK2(d0, __float_as_uint(aA.x));
            PACK2(d1, __float_as_uint(aB.x));
            FFMA2(acc[0][0].u, d0, w0.u[0]); FFMA2(acc[0][1].u, d0, w0.u[1]);
            FFMA2(acc[1][0].u, d1, w0.u[0]); FFMA2(acc[1][1].u, d1, w0.u[1]);
            PACK2(d0, __float_as_uint(aA.y));
            PACK2(d1, __float_as_uint(aB.y));
            FFMA2(acc[0][0].u, d0, w1.u[0]); FFMA2(acc[0][1].u, d0, w1.u[1]);
            FFMA2(acc[1][0].u, d1, w1.u[0]); FFMA2(acc[1][1].u, d1, w1.u[1]);
        }
        __syncthreads();
        buf ^= 1;
    }

    // stage A tile to smem so gates line up per (n, jj)
    #pragma unroll
    for (int r = 0; r < 2; r++) {
        #pragma unroll
        for (int p = 0; p < 2; p++) {
            A_s[n0 + r][c0 + 2 * p + 0] = acc[r][p].f.x;
            A_s[n0 + r][c0 + 2 * p + 1] = acc[r][p].f.y;
        }
    }
    __syncthreads();

    // elementwise gates: 512 (n,jj) pairs, 2 per thread
    #pragma unroll
    for (int q = 0; q < 2; q++) {
        int p  = q * 256 + tid;
        int n  = p >> 3;
        int jj = p & 7;
        size_t xb = (size_t)n * Gg + j0 + jj;
        float ai = A_s[n][0  + jj] + xw[xb + 0 * Hh];
        float af = A_s[n][8  + jj] + xw[xb + 1 * Hh];
        float ao = A_s[n][16 + jj] + xw[xb + 2 * Hh];
        float ag = A_s[n][24 + jj] + xw[xb + 3 * Hh];

        float ig = 1.0f / (1.0f + __expf(-ai));
        float fg = 1.0f / (1.0f + __expf(-af));
        float og = 1.0f / (1.0f + __expf(-ao));
        float gg = tanhf(ag);

        int ci = n * Hh + j0 + jj;
        float cprev = (t == 0) ? 0.0f : g_cbuf[ci];
        float cn = fg * cprev + ig * gg;
        g_cbuf[ci] = cn;
        float hv = og * tanhf(cn);
        h_out[ci] = hv;
        out[((size_t)n * Ts + t) * Hh + j0 + jj] = hv;
    }
}

extern "C" void kernel_launch(void* const* d_in, const int* in_sizes, int n_in,
                              void* d_out, int out_size) {
    const float* x  = (const float*)d_in[0];   // (64, 512, 1024)
    const float* h0 = (const float*)d_in[1];   // (64, 1024)
    const float* Wx = (const float*)d_in[2];   // (1024, 4096)
    const float* Wh = (const float*)d_in[3];   // (1024, 4096)
    const float* b  = (const float*)d_in[4];   // (4096)
    float* out = (float*)d_out;                // (64, 512, 1024)

    dim3 g1(Gg / 128, (Nb * Ts) / 128);        // (32, 256)
    xw_gemm<<<g1, 256>>>(x, Wx, b);

    for (int t = 0; t < Ts; t++) {
        lstm_step<<<Hh / 8, 256>>>(Wh, h0, out, t);
    }
}

// round 9
// speedup vs baseline: 2.3140x; 2.3140x over previous
#include <cuda_runtime.h>
#include <cstddef>

#define Nb 64
#define Ts 512
#define Dd 1024
#define Hh 1024
#define Gg 4096   // 4*Hh

typedef unsigned long long u64;

// Scratch (static device arrays; no allocations).
__device__ float g_xw[(size_t)Nb * Ts * Gg];     // (t, n, 4H)
__device__ float g_hT[2][Hh * Nb];               // transposed h: [k][n], double-buffered
__device__ int   g_bar[Ts];                      // per-step barrier counters

union F2U { u64 u; float2 f; };
union F4U { float4 f; u64 u[2]; };

#define FFMA2(d, a, b) asm("fma.rn.f32x2 %0, %1, %2, %0;" : "+l"(d) : "l"(a), "l"(b))
#define PACK2(d, s)    asm("mov.b64 %0, {%1, %1};" : "=l"(d) : "r"(s))

__device__ __forceinline__ void cp16(void* smem, const void* g) {
    unsigned saddr = (unsigned)__cvta_generic_to_shared(smem);
    asm volatile("cp.async.cg.shared.global [%0], [%1], 16;" :: "r"(saddr), "l"(g));
}
#define CP_COMMIT() asm volatile("cp.async.commit_group;")
#define CP_WAIT1()  asm volatile("cp.async.wait_group 1;")
#define CP_WAIT0()  asm volatile("cp.async.wait_group 0;")

// ===================================================================
// prep: zero per-step barrier counters; transpose h0 -> g_hT[0]
// ===================================================================
__global__ void prep(const float* __restrict__ h0) {
    int tid = blockIdx.x * blockDim.x + threadIdx.x;
    int nt  = gridDim.x * blockDim.x;
    if (tid < Ts) g_bar[tid] = 0;
    for (int i = tid; i < Nb * Hh; i += nt) {
        int k = i >> 6, n = i & 63;         // i = k*64 + n (coalesced writes)
        g_hT[0][i] = h0[n * Hh + k];
    }
}

// ===================================================================
// Kernel 1: xW[t*64+n][g] = bias[g] + sum_d x[n][t][d] * Wx[d][g]
// (unchanged — known correct)
// ===================================================================
__global__ __launch_bounds__(256) void xw_gemm(const float* __restrict__ x,
                                               const float* __restrict__ Wx,
                                               const float* __restrict__ bias) {
    __shared__ float As[2][128][20];
    __shared__ float Bs[2][16][128];

    const int tid  = threadIdx.x;
    const int row0 = blockIdx.y * 128;
    const int col0 = blockIdx.x * 128;
    const int tx = tid & 15, ty = tid >> 4;

    const int arow = tid >> 2;
    const int ak   = (tid & 3) << 2;
    const int brow = tid >> 5;
    const int bcol = (tid & 31) << 2;

    F2U acc[8][4];
    #pragma unroll
    for (int i = 0; i < 8; i++)
        #pragma unroll
        for (int j = 0; j < 4; j++) acc[i][j].u = 0ull;

    {
        #pragma unroll
        for (int rr = 0; rr < 2; rr++) {
            int r = arow + rr * 64;
            int m = row0 + r;
            int t = m >> 6, n = m & 63;
            cp16(&As[0][r][ak], x + ((size_t)n * Ts + t) * Dd + 0 + ak);
        }
        #pragma unroll
        for (int rr = 0; rr < 2; rr++) {
            int rb = brow + rr * 8;
            cp16(&Bs[0][rb][bcol], Wx + (size_t)(0 + rb) * Gg + col0 + bcol);
        }
        CP_COMMIT();
    }

    int buf = 0;
    for (int kt = 0; kt < Dd; kt += 16) {
        if (kt + 16 < Dd) {
            #pragma unroll
            for (int rr = 0; rr < 2; rr++) {
                int r = arow + rr * 64;
                int m = row0 + r;
                int t = m >> 6, n = m & 63;
                cp16(&As[buf ^ 1][r][ak], x + ((size_t)n * Ts + t) * Dd + (kt + 16) + ak);
            }
            #pragma unroll
            for (int rr = 0; rr < 2; rr++) {
                int rb = brow + rr * 8;
                cp16(&Bs[buf ^ 1][rb][bcol], Wx + (size_t)(kt + 16 + rb) * Gg + col0 + bcol);
            }
        }
        CP_COMMIT();
        CP_WAIT1();
        __syncthreads();

        const float (*Asb)[20]  = As[buf];
        const float (*Bsb)[128] = Bs[buf];
        #pragma unroll
        for (int k = 0; k < 16; k++) {
            float a[8];
            #pragma unroll
            for (int i = 0; i < 8; i++) a[i] = Asb[ty * 8 + i][k];
            const u64* bp = (const u64*)&Bsb[k][tx * 8];
            u64 b2[4];
            b2[0] = bp[0]; b2[1] = bp[1]; b2[2] = bp[2]; b2[3] = bp[3];
            #pragma unroll
            for (int i = 0; i < 8; i++) {
                u64 a2; PACK2(a2, __float_as_uint(a[i]));
                FFMA2(acc[i][0].u, a2, b2[0]);
                FFMA2(acc[i][1].u, a2, b2[1]);
                FFMA2(acc[i][2].u, a2, b2[2]);
                FFMA2(acc[i][3].u, a2, b2[3]);
            }
        }
        __syncthreads();
        buf ^= 1;
    }

    #pragma unroll
    for (int i = 0; i < 8; i++) {
        size_t m = (size_t)(row0 + ty * 8 + i);
        float* outp = g_xw + m * Gg + col0 + tx * 8;
        #pragma unroll
        for (int j = 0; j < 4; j++) {
            float2 v = acc[i][j].f;
            v.x += bias[col0 + tx * 8 + 2 * j + 0];
            v.y += bias[col0 + tx * 8 + 2 * j + 1];
            *(float2*)(outp + 2 * j) = v;
        }
    }
}

// ===================================================================
// Kernel 2: persistent LSTM recurrence (race-hardened rewrite).
// 128 CTAs x 512 threads. CTA b owns hidden cols j0=b*8..b*8+7 (x4 gates
// = 32 gate-cols). Wh slice (1024x32 = 128KB) resident in smem.
// 4 K-split groups of 128 threads (K=256 each), thread tile 4n x 4c.
// h streamed via cp.async, double-buffered, with FULL-CTA __syncthreads
// pipeline (2 bars per 32k chunk). Partials in a DEDICATED smem region
// (no aliasing with cp.async destinations). Grid barrier: release-fenced
// atomicAdd arrival + ld.acquire.gpu spin (tid 0 only).
// smem: Wh 131072 + hS 65536 + partials 33792 = 230400 B -> 1 CTA/SM.
// ===================================================================
__global__ __launch_bounds__(512, 1) void lstm_persist(const float* __restrict__ Wh,
                                                       float* __restrict__ out) {
    extern __shared__ float sm[];
    float* Wh_s = sm;                       // [1024][32] = 32768 floats
    float* hS   = sm + 32768;               // 4 groups x 2 stages x 2048 floats
    float* pS   = sm + 32768 + 16384;       // 4 groups x [64][33] = 8448 floats

    const int tid = threadIdx.x;
    const int j0  = blockIdx.x * 8;
    const int g   = tid >> 7;               // K-split group 0..3
    const int tl  = tid & 127;
    const int rg  = tl >> 3;                // row-quad 0..15 (rows rg*4..rg*4+3)
    const int cg  = tl & 7;                 // col-quad 0..7  (cols cg*4..cg*4+3)
    const int n   = tid >> 3;               // gate-stage row 0..63
    const int jj  = tid & 7;                // gate-stage col 0..7

    // ---- load Wh slice into smem (once) ----
    // smem col order: c = gate*8 + jj  (i: 0-7, f: 8-15, o: 16-23, g: 24-31)
    #pragma unroll
    for (int j = 0; j < 16; j++) {
        int idx  = tid + j * 512;           // 0..8191
        int k    = idx >> 3;
        int seg  = idx & 7;
        int gate = seg >> 1, half = seg & 1;
        cp16(Wh_s + k * 32 + gate * 8 + half * 4,
             Wh + (size_t)k * Gg + gate * Hh + j0 + half * 4);
    }
    CP_COMMIT();
    CP_WAIT0();
    __syncthreads();

    float c_reg = 0.0f;                     // cell state, persistent in register
    const int kbase = g * 256;
    float* hs0    = hS + (g * 2) * 2048;    // stage 0 (this group)
    float* hs1    = hs0 + 2048;             // stage 1
    float* mypart = pS + g * 2112;          // [64][33] partials (this group)

    for (int t = 0; t < Ts; t++) {
        const float* hT  = g_hT[t & 1];
        float*       hTo = g_hT[(t + 1) & 1];

        // prefetch xW addends early (DRAM latency hidden behind the GEMM)
        const float* xwp = g_xw + ((size_t)t * Nb + n) * Gg + j0 + jj;
        float xi = xwp[0], xf = xwp[Hh], xo = xwp[2 * Hh], xg = xwp[3 * Hh];

        F2U acc[4][2];
        #pragma unroll
        for (int r = 0; r < 4; r++) { acc[r][0].u = 0ull; acc[r][1].u = 0ull; }

        // prologue: stage chunk 0 into hs0 (32 k x 64 n = 8KB, contiguous)
        {
            const float* src = hT + kbase * 64;
            #pragma unroll
            for (int j = 0; j < 4; j++) {
                int i = tl + j * 128;
                cp16(hs0 + i * 4, src + i * 4);
            }
            CP_COMMIT();
        }

        #pragma unroll 1
        for (int ch = 0; ch < 8; ch++) {
            float* cur = (ch & 1) ? hs1 : hs0;
            float* nxt = (ch & 1) ? hs0 : hs1;
            if (ch < 7) {
                const float* src = hT + (kbase + (ch + 1) * 32) * 64;
                #pragma unroll
                for (int j = 0; j < 4; j++) {
                    int i = tl + j * 128;
                    cp16(nxt + i * 4, src + i * 4);
                }
            }
            CP_COMMIT();
            CP_WAIT1();
            __syncthreads();                // (A) chunk ch landed, CTA-wide

            const float* hb = cur;                             // [32][64]
            const float* wb = Wh_s + (kbase + ch * 32) * 32;   // [32][32]
            #pragma unroll 8
            for (int kk = 0; kk < 32; kk++) {
                float4 h4 = *(const float4*)(hb + kk * 64 + rg * 4);
                F4U w; w.f = *(const float4*)(wb + kk * 32 + cg * 4);
                u64 a0, a1, a2, a3;
                PACK2(a0, __float_as_uint(h4.x));
                PACK2(a1, __float_as_uint(h4.y));
                PACK2(a2, __float_as_uint(h4.z));
                PACK2(a3, __float_as_uint(h4.w));
                FFMA2(acc[0][0].u, a0, w.u[0]); FFMA2(acc[0][1].u, a0, w.u[1]);
                FFMA2(acc[1][0].u, a1, w.u[0]); FFMA2(acc[1][1].u, a1, w.u[1]);
                FFMA2(acc[2][0].u, a2, w.u[0]); FFMA2(acc[2][1].u, a2, w.u[1]);
                FFMA2(acc[3][0].u, a3, w.u[0]); FFMA2(acc[3][1].u, a3, w.u[1]);
            }
            __syncthreads();                // (B) done reading cur before it is rewritten
        }

        // write K-split partials to the DEDICATED region (scalar stores, [64][33])
        #pragma unroll
        for (int r = 0; r < 4; r++) {
            int row = rg * 4 + r;
            float* p = mypart + row * 33 + cg * 4;
            p[0] = acc[r][0].f.x; p[1] = acc[r][0].f.y;
            p[2] = acc[r][1].f.x; p[3] = acc[r][1].f.y;
        }
        __syncthreads();

        // gates: reduce 4 partials + xW, update c (register), emit h
        float Ai = xi, Af = xf, Ao = xo, Ag = xg;
        #pragma unroll
        for (int gr = 0; gr < 4; gr++) {
            const float* p = pS + gr * 2112 + n * 33;
            Ai += p[jj]; Af += p[8 + jj]; Ao += p[16 + jj]; Ag += p[24 + jj];
        }
        float ig = 1.0f / (1.0f + __expf(-Ai));
        float fg = 1.0f / (1.0f + __expf(-Af));
        float og = 1.0f / (1.0f + __expf(-Ao));
        float gg = tanhf(Ag);
        c_reg = fg * c_reg + ig * gg;
        float hv = og * tanhf(c_reg);

        out[((size_t)n * Ts + t) * Hh + j0 + jj] = hv;
        hTo[(j0 + jj) * 64 + n] = hv;

        // ---- grid barrier over 128 CTAs (release arrival / acquire spin) ----
        __syncthreads();
        if (tid == 0) {
            __threadfence();                              // release prior writes
            atomicAdd(&g_bar[t], 1);
            int v;
            do {
                asm volatile("ld.acquire.gpu.global.b32 %0, [%1];"
                             : "=r"(v) : "l"(g_bar + t) : "memory");
            } while (v < 128);
            __threadfence();
        }
        __syncthreads();
    }
}

extern "C" void kernel_launch(void* const* d_in, const int* in_sizes, int n_in,
                              void* d_out, int out_size) {
    const float* x  = (const float*)d_in[0];   // (64, 512, 1024)
    const float* h0 = (const float*)d_in[1];   // (64, 1024)
    const float* Wx = (const float*)d_in[2];   // (1024, 4096)
    const float* Wh = (const float*)d_in[3];   // (1024, 4096)
    const float* b  = (const float*)d_in[4];   // (4096)
    float* out = (float*)d_out;                // (64, 512, 1024)

    cudaFuncSetAttribute(lstm_persist, cudaFuncAttributeMaxDynamicSharedMemorySize, 230400);

    prep<<<64, 256>>>(h0);

    dim3 g1(Gg / 128, (Nb * Ts) / 128);        // (32, 256)
    xw_gemm<<<g1, 256>>>(x, Wx, b);

    lstm_persist<<<128, 512, 230400>>>(Wh, out);
}

// round 10
// speedup vs baseline: 2.5390x; 1.0972x over previous
#include <cuda_runtime.h>
#include <cstddef>

#define Nb 64
#define Ts 512
#define Dd 1024
#define Hh 1024
#define Gg 4096   // 4*Hh

typedef unsigned long long u64;

// Scratch (static device arrays; no allocations).
__device__ float g_xw[(size_t)Nb * Ts * Gg];     // (t, n, 4H)
__device__ float g_hT[2][Hh * Nb];               // transposed h: [k][n], double-buffered
__device__ int   g_barq[Ts][4];                  // per-step, per-quarter barrier counters

union F2U { u64 u; float2 f; };
union F4U { float4 f; u64 u[2]; };

#define FFMA2(d, a, b) asm("fma.rn.f32x2 %0, %1, %2, %0;" : "+l"(d) : "l"(a), "l"(b))
#define PACK2(d, s)    asm("mov.b64 %0, {%1, %1};" : "=l"(d) : "r"(s))

__device__ __forceinline__ void cp16(void* smem, const void* g) {
    unsigned saddr = (unsigned)__cvta_generic_to_shared(smem);
    asm volatile("cp.async.cg.shared.global [%0], [%1], 16;" :: "r"(saddr), "l"(g));
}
#define CP_COMMIT() asm volatile("cp.async.commit_group;")
#define CP_WAIT1()  asm volatile("cp.async.wait_group 1;")
#define CP_WAIT0()  asm volatile("cp.async.wait_group 0;")

// ===================================================================
// prep: zero per-step quarter-barrier counters; transpose h0 -> g_hT[0]
// ===================================================================
__global__ void prep(const float* __restrict__ h0) {
    int tid = blockIdx.x * blockDim.x + threadIdx.x;
    int nt  = gridDim.x * blockDim.x;
    if (tid < Ts * 4) ((int*)g_barq)[tid] = 0;
    for (int i = tid; i < Nb * Hh; i += nt) {
        int k = i >> 6, n = i & 63;         // i = k*64 + n (coalesced writes)
        g_hT[0][i] = h0[n * Hh + k];
    }
}

// ===================================================================
// Kernel 1: xW[t*64+n][g] = bias[g] + sum_d x[n][t][d] * Wx[d][g]
// Now 2 CTAs/SM for latency hiding (regs capped at 128).
// ===================================================================
__global__ __launch_bounds__(256, 2) void xw_gemm(const float* __restrict__ x,
                                                  const float* __restrict__ Wx,
                                                  const float* __restrict__ bias) {
    __shared__ float As[2][128][20];
    __shared__ float Bs[2][16][128];

    const int tid  = threadIdx.x;
    const int row0 = blockIdx.y * 128;
    const int col0 = blockIdx.x * 128;
    const int tx = tid & 15, ty = tid >> 4;

    const int arow = tid >> 2;
    const int ak   = (tid & 3) << 2;
    const int brow = tid >> 5;
    const int bcol = (tid & 31) << 2;

    F2U acc[8][4];
    #pragma unroll
    for (int i = 0; i < 8; i++)
        #pragma unroll
        for (int j = 0; j < 4; j++) acc[i][j].u = 0ull;

    {
        #pragma unroll
        for (int rr = 0; rr < 2; rr++) {
            int r = arow + rr * 64;
            int m = row0 + r;
            int t = m >> 6, n = m & 63;
            cp16(&As[0][r][ak], x + ((size_t)n * Ts + t) * Dd + 0 + ak);
        }
        #pragma unroll
        for (int rr = 0; rr < 2; rr++) {
            int rb = brow + rr * 8;
            cp16(&Bs[0][rb][bcol], Wx + (size_t)(0 + rb) * Gg + col0 + bcol);
        }
        CP_COMMIT();
    }

    int buf = 0;
    for (int kt = 0; kt < Dd; kt += 16) {
        if (kt + 16 < Dd) {
            #pragma unroll
            for (int rr = 0; rr < 2; rr++) {
                int r = arow + rr * 64;
                int m = row0 + r;
                int t = m >> 6, n = m & 63;
                cp16(&As[buf ^ 1][r][ak], x + ((size_t)n * Ts + t) * Dd + (kt + 16) + ak);
            }
            #pragma unroll
            for (int rr = 0; rr < 2; rr++) {
                int rb = brow + rr * 8;
                cp16(&Bs[buf ^ 1][rb][bcol], Wx + (size_t)(kt + 16 + rb) * Gg + col0 + bcol);
            }
        }
        CP_COMMIT();
        CP_WAIT1();
        __syncthreads();

        const float (*Asb)[20]  = As[buf];
        const float (*Bsb)[128] = Bs[buf];
        #pragma unroll
        for (int k = 0; k < 16; k++) {
            float a[8];
            #pragma unroll
            for (int i = 0; i < 8; i++) a[i] = Asb[ty * 8 + i][k];
            const u64* bp = (const u64*)&Bsb[k][tx * 8];
            u64 b2[4];
            b2[0] = bp[0]; b2[1] = bp[1]; b2[2] = bp[2]; b2[3] = bp[3];
            #pragma unroll
            for (int i = 0; i < 8; i++) {
                u64 a2; PACK2(a2, __float_as_uint(a[i]));
                FFMA2(acc[i][0].u, a2, b2[0]);
                FFMA2(acc[i][1].u, a2, b2[1]);
                FFMA2(acc[i][2].u, a2, b2[2]);
                FFMA2(acc[i][3].u, a2, b2[3]);
            }
        }
        __syncthreads();
        buf ^= 1;
    }

    #pragma unroll
    for (int i = 0; i < 8; i++) {
        size_t m = (size_t)(row0 + ty * 8 + i);
        float* outp = g_xw + m * Gg + col0 + tx * 8;
        #pragma unroll
        for (int j = 0; j < 4; j++) {
            float2 v = acc[i][j].f;
            v.x += bias[col0 + tx * 8 + 2 * j + 0];
            v.y += bias[col0 + tx * 8 + 2 * j + 1];
            *(float2*)(outp + 2 * j) = v;
        }
    }
}

// ===================================================================
// Kernel 2: persistent LSTM recurrence, quarter-barrier version.
// 128 CTAs x 512 threads. CTA b owns hidden cols j0=b*8..b*8+7 (x4 gates).
// Wh slice (1024x32 = 128KB) resident in smem. 4 K-split groups of 128
// threads (K=256 each). Group g's input (hT rows 256g..256g+255) is
// produced exactly by CTA quarter g (CTAs 32g..32g+31), so each group
// waits only on its quarter's counter -> staggered start, skew absorbed.
// Chunk pipeline uses per-group named barriers (bar.sync g+1, 128) with
// the same 2-bar ordering as the passing R9 CTA-wide version.
// Partials in a dedicated smem region; gates after a CTA-wide sync.
// Safety: a CTA writes h for step t only after observing ALL quarters
// complete step t-1 (its 4 groups' spins + CTA sync) -> max lag < 2
// steps -> the double-buffered hT WAR is safe.
// smem: Wh 131072 + hS 65536 + partials 33792 = 230400 B -> 1 CTA/SM.
// ===================================================================
__global__ __launch_bounds__(512, 1) void lstm_persist(const float* __restrict__ Wh,
                                                       float* __restrict__ out) {
    extern __shared__ float sm[];
    float* Wh_s = sm;                       // [1024][32] = 32768 floats
    float* hS   = sm + 32768;               // 4 groups x 2 stages x 2048 floats
    float* pS   = sm + 32768 + 16384;       // 4 groups x [64][33] = 8448 floats

    const int tid = threadIdx.x;
    const int j0  = blockIdx.x * 8;
    const int quarter = blockIdx.x >> 5;    // which quarter this CTA's h cols feed
    const int g   = tid >> 7;               // K-split group 0..3
    const int tl  = tid & 127;
    const int rg  = tl >> 3;                // row-quad 0..15 (rows rg*4..rg*4+3)
    const int cg  = tl & 7;                 // col-quad 0..7  (cols cg*4..cg*4+3)
    const int n   = tid >> 3;               // gate-stage row 0..63
    const int jj  = tid & 7;                // gate-stage col 0..7

    // ---- load Wh slice into smem (once) ----
    // smem col order: c = gate*8 + jj  (i: 0-7, f: 8-15, o: 16-23, g: 24-31)
    #pragma unroll
    for (int j = 0; j < 16; j++) {
        int idx  = tid + j * 512;           // 0..8191
        int k    = idx >> 3;
        int seg  = idx & 7;
        int gate = seg >> 1, half = seg & 1;
        cp16(Wh_s + k * 32 + gate * 8 + half * 4,
             Wh + (size_t)k * Gg + gate * Hh + j0 + half * 4);
    }
    CP_COMMIT();
    CP_WAIT0();
    __syncthreads();

    float c_reg = 0.0f;                     // cell state, persistent in register
    const int kbase = g * 256;
    float* hs0    = hS + (g * 2) * 2048;    // stage 0 (this group)
    float* hs1    = hs0 + 2048;             // stage 1
    float* mypart = pS + g * 2112;          // [64][33] partials (this group)

    for (int t = 0; t < Ts; t++) {
        const float* hT  = g_hT[t & 1];
        float*       hTo = g_hT[(t + 1) & 1];

        // prefetch xW addends first (DRAM latency overlaps the spin below)
        const float* xwp = g_xw + ((size_t)t * Nb + n) * Gg + j0 + jj;
        float xi = xwp[0], xf = xwp[Hh], xo = xwp[2 * Hh], xg = xwp[3 * Hh];

        // ---- per-group input-ready wait: quarter g published step-t input ----
        if (t > 0) {
            if (tl == 0) {
                int v;
                do {
                    asm volatile("ld.acquire.gpu.global.b32 %0, [%1];"
                                 : "=r"(v) : "l"(&g_barq[t - 1][g]) : "memory");
                } while (v < 32);
            }
            asm volatile("bar.sync %0, 128;" :: "r"(g + 1) : "memory");
        }

        F2U acc[4][2];
        #pragma unroll
        for (int r = 0; r < 4; r++) { acc[r][0].u = 0ull; acc[r][1].u = 0ull; }

        // prologue: stage chunk 0 into hs0 (32 k x 64 n = 8KB, contiguous)
        {
            const float* src = hT + kbase * 64;
            #pragma unroll
            for (int j = 0; j < 4; j++) {
                int i = tl + j * 128;
                cp16(hs0 + i * 4, src + i * 4);
            }
            CP_COMMIT();
        }

        #pragma unroll 1
        for (int ch = 0; ch < 8; ch++) {
            float* cur = (ch & 1) ? hs1 : hs0;
            float* nxt = (ch & 1) ? hs0 : hs1;
            if (ch < 7) {
                const float* src = hT + (kbase + (ch + 1) * 32) * 64;
                #pragma unroll
                for (int j = 0; j < 4; j++) {
                    int i = tl + j * 128;
                    cp16(nxt + i * 4, src + i * 4);
                }
            }
            CP_COMMIT();
            CP_WAIT1();
            asm volatile("bar.sync %0, 128;" :: "r"(g + 1) : "memory"); // (A) chunk landed

            const float* hb = cur;                             // [32][64]
            const float* wb = Wh_s + (kbase + ch * 32) * 32;   // [32][32]
            #pragma unroll 8
            for (int kk = 0; kk < 32; kk++) {
                float4 h4 = *(const float4*)(hb + kk * 64 + rg * 4);
                F4U w; w.f = *(const float4*)(wb + kk * 32 + cg * 4);
                u64 a0, a1, a2, a3;
                PACK2(a0, __float_as_uint(h4.x));
                PACK2(a1, __float_as_uint(h4.y));
                PACK2(a2, __float_as_uint(h4.z));
                PACK2(a3, __float_as_uint(h4.w));
                FFMA2(acc[0][0].u, a0, w.u[0]); FFMA2(acc[0][1].u, a0, w.u[1]);
                FFMA2(acc[1][0].u, a1, w.u[0]); FFMA2(acc[1][1].u, a1, w.u[1]);
                FFMA2(acc[2][0].u, a2, w.u[0]); FFMA2(acc[2][1].u, a2, w.u[1]);
                FFMA2(acc[3][0].u, a3, w.u[0]); FFMA2(acc[3][1].u, a3, w.u[1]);
            }
            asm volatile("bar.sync %0, 128;" :: "r"(g + 1) : "memory"); // (B) cur free
        }

        // write K-split partials to the DEDICATED region ([64][33])
        #pragma unroll
        for (int r = 0; r < 4; r++) {
            int row = rg * 4 + r;
            float* p = mypart + row * 33 + cg * 4;
            p[0] = acc[r][0].f.x; p[1] = acc[r][0].f.y;
            p[2] = acc[r][1].f.x; p[3] = acc[r][1].f.y;
        }
        __syncthreads();   // CTA-wide: all groups' partials visible; also orders
                           // every group's quarter-spin before the h writes below

        // gates: reduce 4 partials + xW, update c (register), emit h
        float Ai = xi, Af = xf, Ao = xo, Ag = xg;
        #pragma unroll
        for (int gr = 0; gr < 4; gr++) {
            const float* p = pS + gr * 2112 + n * 33;
            Ai += p[jj]; Af += p[8 + jj]; Ao += p[16 + jj]; Ag += p[24 + jj];
        }
        float ig = 1.0f / (1.0f + __expf(-Ai));
        float fg = 1.0f / (1.0f + __expf(-Af));
        float og = 1.0f / (1.0f + __expf(-Ao));
        float gg = tanhf(Ag);
        c_reg = fg * c_reg + ig * gg;
        float hv = og * tanhf(c_reg);

        out[((size_t)n * Ts + t) * Hh + j0 + jj] = hv;
        hTo[(j0 + jj) * 64 + n] = hv;

        // ---- publish: this CTA's h columns for step t+1 are ready ----
        __syncthreads();                      // all 512 threads' hTo writes done
        if (tid == 0) {
            __threadfence();                  // release h writes gpu-wide
            atomicAdd(&g_barq[t][quarter], 1);
        }
    }
}

extern "C" void kernel_launch(void* const* d_in, const int* in_sizes, int n_in,
                              void* d_out, int out_size) {
    const float* x  = (const float*)d_in[0];   // (64, 512, 1024)
    const float* h0 = (const float*)d_in[1];   // (64, 1024)
    const float* Wx = (const float*)d_in[2];   // (1024, 4096)
    const float* Wh = (const float*)d_in[3];   // (1024, 4096)
    const float* b  = (const float*)d_in[4];   // (4096)
    float* out = (float*)d_out;                // (64, 512, 1024)

    cudaFuncSetAttribute(lstm_persist, cudaFuncAttributeMaxDynamicSharedMemorySize, 230400);

    prep<<<64, 256>>>(h0);

    dim3 g1(Gg / 128, (Nb * Ts) / 128);        // (32, 256)
    xw_gemm<<<g1, 256>>>(x, Wx, b);

    lstm_persist<<<128, 512, 230400>>>(Wh, out);
}

// round 12
// speedup vs baseline: 3.1559x; 1.2430x over previous
#include <cuda_runtime.h>
#include <cuda_bf16.h>
#include <cstddef>
#include <cstdint>

#define Nb 64
#define Ts 512
#define Dd 1024
#define Hh 1024
#define Gg 4096   // 4*Hh

typedef unsigned long long u64;

// Scratch (static device arrays; no allocations).
__device__ float g_xw[(size_t)Nb * Ts * Gg];     // (t, n, 4H)
__device__ float g_hT[2][Hh * Nb];               // transposed h: [k][n], double-buffered
__device__ int   g_barq[Ts][4];                  // per-step, per-quarter barrier counters

// bf16-split operands for the tensor-core input GEMM.
__device__ __align__(16) __nv_bfloat16 g_Ah[(size_t)Nb * Ts * Dd];  // A hi [m][d], m=t*64+n
__device__ __align__(16) __nv_bfloat16 g_Al[(size_t)Nb * Ts * Dd];  // A lo
__device__ __align__(16) __nv_bfloat16 g_Bh[(size_t)Gg * Dd];       // Wx^T hi [g][d]
__device__ __align__(16) __nv_bfloat16 g_Bl[(size_t)Gg * Dd];       // Wx^T lo

union F2U { u64 u; float2 f; };
union F4U { float4 f; u64 u[2]; };

#define FFMA2(d, a, b) asm("fma.rn.f32x2 %0, %1, %2, %0;" : "+l"(d) : "l"(a), "l"(b))
#define PACK2(d, s)    asm("mov.b64 %0, {%1, %1};" : "=l"(d) : "r"(s))

__device__ __forceinline__ void cp16(void* smem, const void* g) {
    unsigned saddr = (unsigned)__cvta_generic_to_shared(smem);
    asm volatile("cp.async.cg.shared.global [%0], [%1], 16;" :: "r"(saddr), "l"(g));
}
#define CP_COMMIT() asm volatile("cp.async.commit_group;")
#define CP_WAIT1()  asm volatile("cp.async.wait_group 1;")
#define CP_WAIT0()  asm volatile("cp.async.wait_group 0;")

// mma.sync m16n8k16 row.col f32.bf16.bf16.f32 — baseline PTX, no 'a' target needed.
#define MMA16816(c, a, b) \
    asm volatile("mma.sync.aligned.m16n8k16.row.col.f32.bf16.bf16.f32 " \
                 "{%0,%1,%2,%3}, {%4,%5,%6,%7}, {%8,%9}, {%0,%1,%2,%3};" \
                 : "+f"((c)[0]), "+f"((c)[1]), "+f"((c)[2]), "+f"((c)[3]) \
                 : "r"((a)[0]), "r"((a)[1]), "r"((a)[2]), "r"((a)[3]), \
                   "r"((b)[0]), "r"((b)[1]))

// ===================================================================
// prep: zero per-step quarter-barrier counters; transpose h0 -> g_hT[0]
// ===================================================================
__global__ void prep(const float* __restrict__ h0) {
    int tid = blockIdx.x * blockDim.x + threadIdx.x;
    int nt  = gridDim.x * blockDim.x;
    if (tid < Ts * 4) ((int*)g_barq)[tid] = 0;
    for (int i = tid; i < Nb * Hh; i += nt) {
        int k = i >> 6, n = i & 63;
        g_hT[0][i] = h0[n * Hh + k];
    }
}

// ===================================================================
// conv_x: x (N,T,D) fp32 -> bf16 hi/lo rows m = t*64+n.
// ===================================================================
__global__ void conv_x(const float* __restrict__ x) {
    size_t u = (size_t)blockIdx.x * blockDim.x + threadIdx.x;   // 4,194,304 threads
    int m  = (int)(u >> 7);
    int d0 = (int)(u & 127) << 3;
    int t = m >> 6, n = m & 63;
    const float* src = x + ((size_t)n * Ts + t) * Dd + d0;
    float4 v0 = *(const float4*)src;
    float4 v1 = *(const float4*)(src + 4);
    float vv[8] = {v0.x, v0.y, v0.z, v0.w, v1.x, v1.y, v1.z, v1.w};
    union { __nv_bfloat16 b[8]; uint4 q; } H, L;
    #pragma unroll
    for (int j = 0; j < 8; j++) {
        __nv_bfloat16 h = __float2bfloat16(vv[j]);
        H.b[j] = h;
        L.b[j] = __float2bfloat16(vv[j] - __bfloat162float(h));
    }
    *(uint4*)(g_Ah + (size_t)m * Dd + d0) = H.q;
    *(uint4*)(g_Al + (size_t)m * Dd + d0) = L.q;
}

// ===================================================================
// conv_w: Wx [d][g] fp32 -> transposed bf16 hi/lo [g][d].
// ===================================================================
__global__ void conv_w(const float* __restrict__ Wx) {
    size_t u = (size_t)blockIdx.x * blockDim.x + threadIdx.x;   // 524,288 threads
    int g  = (int)(u & 4095);
    int d0 = (int)(u >> 12) << 3;
    union { __nv_bfloat16 b[8]; uint4 q; } H, L;
    #pragma unroll
    for (int j = 0; j < 8; j++) {
        float v = Wx[(size_t)(d0 + j) * Gg + g];
        __nv_bfloat16 h = __float2bfloat16(v);
        H.b[j] = h;
        L.b[j] = __float2bfloat16(v - __bfloat162float(h));
    }
    *(uint4*)(g_Bh + (size_t)g * Dd + d0) = H.q;
    *(uint4*)(g_Bl + (size_t)g * Dd + d0) = L.q;
}

// ===================================================================
// tc_gemm: xW = A @ B^T + bias via mma.sync (HMMA bf16, baseline PTX).
// BM=128, BN=128, BK=32, 256 threads = 8 warps (2 M x 4 N), warp tile
// 64x32 (4 m16 x 4 n8 tiles). bf16-split 3-term: ah*bh + ah*bl + al*bh.
// cp.async double-buffered; fragments via direct 32-bit LDS from padded
// [128][40] bf16 smem (conflict-free: group*20+tg covers all 32 banks).
// 2 CTAs/SM (81,920 B smem each) overlap memory with math.
// ===================================================================
typedef __nv_bfloat16 bf16;
typedef bf16 SmTile[128][40];    // 10,240 B per tile

__global__ __launch_bounds__(256, 2) void tc_gemm(const float* __restrict__ bias) {
    extern __shared__ bf16 smraw[];
    SmTile* tiles = (SmTile*)smraw;    // [buf*4 + {Ah,Al,Bh,Bl}]

    const int tid = threadIdx.x;
    const int wid = tid >> 5;
    const int lid = tid & 31;
    const int grp = lid >> 2;          // 0..7
    const int tg  = lid & 3;           // 0..3
    const int wm  = wid >> 2;          // 0..1 -> M offset wm*64
    const int wn  = wid & 3;           // 0..3 -> N offset wn*32
    const int n0  = blockIdx.x * 128;  // N fastest: A tile L2-reused across 32 CTAs
    const int m0  = blockIdx.y * 128;

    // load map: per tile 512 16B-chunks; this thread does chunks tid*2, tid*2+1
    #define LOADTILES(buf, kt) do { \
        _Pragma("unroll") \
        for (int q = 0; q < 2; q++) { \
            int c  = tid * 2 + q; \
            int r  = c >> 2; \
            int kc = (c & 3) * 8; \
            size_t goff = (size_t)r * Dd + (kt) + kc; \
            cp16(&tiles[(buf)*4 + 0][r][kc], g_Ah + (size_t)m0 * Dd + goff); \
            cp16(&tiles[(buf)*4 + 1][r][kc], g_Al + (size_t)m0 * Dd + goff); \
            cp16(&tiles[(buf)*4 + 2][r][kc], g_Bh + (size_t)n0 * Dd + goff); \
            cp16(&tiles[(buf)*4 + 3][r][kc], g_Bl + (size_t)n0 * Dd + goff); \
        } \
    } while (0)

    float acc[4][4][4];
    #pragma unroll
    for (int mt = 0; mt < 4; mt++)
        #pragma unroll
        for (int nt = 0; nt < 4; nt++)
            #pragma unroll
            for (int e = 0; e < 4; e++) acc[mt][nt][e] = 0.0f;

    LOADTILES(0, 0);
    CP_COMMIT();

    int buf = 0;
    for (int kt = 0; kt < Dd; kt += 32) {
        if (kt + 32 < Dd) LOADTILES(buf ^ 1, kt + 32);
        CP_COMMIT();
        CP_WAIT1();
        __syncthreads();

        const SmTile& Ah_s = tiles[buf * 4 + 0];
        const SmTile& Al_s = tiles[buf * 4 + 1];
        const SmTile& Bh_s = tiles[buf * 4 + 2];
        const SmTile& Bl_s = tiles[buf * 4 + 3];

        #pragma unroll
        for (int ks = 0; ks < 32; ks += 16) {
            uint32_t af[4][4], bfr[4][2];
            const int k0 = ks + tg * 2;

            // term 1: ah * bh
            #pragma unroll
            for (int mt = 0; mt < 4; mt++) {
                int r = wm * 64 + mt * 16 + grp;
                af[mt][0] = *(const uint32_t*)&Ah_s[r][k0];
                af[mt][1] = *(const uint32_t*)&Ah_s[r + 8][k0];
                af[mt][2] = *(const uint32_t*)&Ah_s[r][k0 + 8];
                af[mt][3] = *(const uint32_t*)&Ah_s[r + 8][k0 + 8];
            }
            #pragma unroll
            for (int nt = 0; nt < 4; nt++) {
                int r = wn * 32 + nt * 8 + grp;
                bfr[nt][0] = *(const uint32_t*)&Bh_s[r][k0];
                bfr[nt][1] = *(const uint32_t*)&Bh_s[r][k0 + 8];
            }
            #pragma unroll
            for (int mt = 0; mt < 4; mt++)
                #pragma unroll
                for (int nt = 0; nt < 4; nt++)
                    MMA16816(acc[mt][nt], af[mt], bfr[nt]);

            // term 2: ah * bl (reuse af)
            #pragma unroll
            for (int nt = 0; nt < 4; nt++) {
                int r = wn * 32 + nt * 8 + grp;
                bfr[nt][0] = *(const uint32_t*)&Bl_s[r][k0];
                bfr[nt][1] = *(const uint32_t*)&Bl_s[r][k0 + 8];
            }
            #pragma unroll
            for (int mt = 0; mt < 4; mt++)
                #pragma unroll
                for (int nt = 0; nt < 4; nt++)
                    MMA16816(acc[mt][nt], af[mt], bfr[nt]);

            // term 3: al * bh (reload both)
            #pragma unroll
            for (int mt = 0; mt < 4; mt++) {
                int r = wm * 64 + mt * 16 + grp;
                af[mt][0] = *(const uint32_t*)&Al_s[r][k0];
                af[mt][1] = *(const uint32_t*)&Al_s[r + 8][k0];
                af[mt][2] = *(const uint32_t*)&Al_s[r][k0 + 8];
                af[mt][3] = *(const uint32_t*)&Al_s[r + 8][k0 + 8];
            }
            #pragma unroll
            for (int nt = 0; nt < 4; nt++) {
                int r = wn * 32 + nt * 8 + grp;
                bfr[nt][0] = *(const uint32_t*)&Bh_s[r][k0];
                bfr[nt][1] = *(const uint32_t*)&Bh_s[r][k0 + 8];
            }
            #pragma unroll
            for (int mt = 0; mt < 4; mt++)
                #pragma unroll
                for (int nt = 0; nt < 4; nt++)
                    MMA16816(acc[mt][nt], af[mt], bfr[nt]);
        }
        __syncthreads();
        buf ^= 1;
    }

    // epilogue: bias + store (c0,c1 at row grp; c2,c3 at row grp+8)
    #pragma unroll
    for (int mt = 0; mt < 4; mt++) {
        int mrow = m0 + wm * 64 + mt * 16 + grp;
        #pragma unroll
        for (int nt = 0; nt < 4; nt++) {
            int col = n0 + wn * 32 + nt * 8 + tg * 2;
            float2 bv = *(const float2*)(bias + col);
            float2 v0 = make_float2(acc[mt][nt][0] + bv.x, acc[mt][nt][1] + bv.y);
            float2 v1 = make_float2(acc[mt][nt][2] + bv.x, acc[mt][nt][3] + bv.y);
            *(float2*)(g_xw + (size_t)mrow * Gg + col) = v0;
            *(float2*)(g_xw + (size_t)(mrow + 8) * Gg + col) = v1;
        }
    }
    #undef LOADTILES
}

// ===================================================================
// Kernel 2: persistent LSTM recurrence (UNCHANGED from passing R10).
// ===================================================================
__global__ __launch_bounds__(512, 1) void lstm_persist(const float* __restrict__ Wh,
                                                       float* __restrict__ out) {
    extern __shared__ float sm[];
    float* Wh_s = sm;                       // [1024][32] = 32768 floats
    float* hS   = sm + 32768;               // 4 groups x 2 stages x 2048 floats
    float* pS   = sm + 32768 + 16384;       // 4 groups x [64][33] = 8448 floats

    const int tid = threadIdx.x;
    const int j0  = blockIdx.x * 8;
    const int quarter = blockIdx.x >> 5;
    const int g   = tid >> 7;
    const int tl  = tid & 127;
    const int rg  = tl >> 3;
    const int cg  = tl & 7;
    const int n   = tid >> 3;
    const int jj  = tid & 7;

    #pragma unroll
    for (int j = 0; j < 16; j++) {
        int idx  = tid + j * 512;
        int k    = idx >> 3;
        int seg  = idx & 7;
        int gate = seg >> 1, half = seg & 1;
        cp16(Wh_s + k * 32 + gate * 8 + half * 4,
             Wh + (size_t)k * Gg + gate * Hh + j0 + half * 4);
    }
    CP_COMMIT();
    CP_WAIT0();
    __syncthreads();

    float c_reg = 0.0f;
    const int kbase = g * 256;
    float* hs0    = hS + (g * 2) * 2048;
    float* hs1    = hs0 + 2048;
    float* mypart = pS + g * 2112;

    for (int t = 0; t < Ts; t++) {
        const float* hT  = g_hT[t & 1];
        float*       hTo = g_hT[(t + 1) & 1];

        const float* xwp = g_xw + ((size_t)t * Nb + n) * Gg + j0 + jj;
        float xi = xwp[0], xf = xwp[Hh], xo = xwp[2 * Hh], xg = xwp[3 * Hh];

        if (t > 0) {
            if (tl == 0) {
                int v;
                do {
                    asm volatile("ld.acquire.gpu.global.b32 %0, [%1];"
                                 : "=r"(v) : "l"(&g_barq[t - 1][g]) : "memory");
                } while (v < 32);
            }
            asm volatile("bar.sync %0, 128;" :: "r"(g + 1) : "memory");
        }

        F2U acc[4][2];
        #pragma unroll
        for (int r = 0; r < 4; r++) { acc[r][0].u = 0ull; acc[r][1].u = 0ull; }

        {
            const float* src = hT + kbase * 64;
            #pragma unroll
            for (int j = 0; j < 4; j++) {
                int i = tl + j * 128;
                cp16(hs0 + i * 4, src + i * 4);
            }
            CP_COMMIT();
        }

        #pragma unroll 1
        for (int ch = 0; ch < 8; ch++) {
            float* cur = (ch & 1) ? hs1 : hs0;
            float* nxt = (ch & 1) ? hs0 : hs1;
            if (ch < 7) {
                const float* src = hT + (kbase + (ch + 1) * 32) * 64;
                #pragma unroll
                for (int j = 0; j < 4; j++) {
                    int i = tl + j * 128;
                    cp16(nxt + i * 4, src + i * 4);
                }
            }
            CP_COMMIT();
            CP_WAIT1();
            asm volatile("bar.sync %0, 128;" :: "r"(g + 1) : "memory");

            const float* hb = cur;
            const float* wb = Wh_s + (kbase + ch * 32) * 32;
            #pragma unroll 8
            for (int kk = 0; kk < 32; kk++) {
                float4 h4 = *(const float4*)(hb + kk * 64 + rg * 4);
                F4U w; w.f = *(const float4*)(wb + kk * 32 + cg * 4);
                u64 a0, a1, a2, a3;
                PACK2(a0, __float_as_uint(h4.x));
                PACK2(a1, __float_as_uint(h4.y));
                PACK2(a2, __float_as_uint(h4.z));
                PACK2(a3, __float_as_uint(h4.w));
                FFMA2(acc[0][0].u, a0, w.u[0]); FFMA2(acc[0][1].u, a0, w.u[1]);
                FFMA2(acc[1][0].u, a1, w.u[0]); FFMA2(acc[1][1].u, a1, w.u[1]);
                FFMA2(acc[2][0].u, a2, w.u[0]); FFMA2(acc[2][1].u, a2, w.u[1]);
                FFMA2(acc[3][0].u, a3, w.u[0]); FFMA2(acc[3][1].u, a3, w.u[1]);
            }
            asm volatile("bar.sync %0, 128;" :: "r"(g + 1) : "memory");
        }

        #pragma unroll
        for (int r = 0; r < 4; r++) {
            int row = rg * 4 + r;
            float* p = mypart + row * 33 + cg * 4;
            p[0] = acc[r][0].f.x; p[1] = acc[r][0].f.y;
            p[2] = acc[r][1].f.x; p[3] = acc[r][1].f.y;
        }
        __syncthreads();

        float Ai = xi, Af = xf, Ao = xo, Ag = xg;
        #pragma unroll
        for (int gr = 0; gr < 4; gr++) {
            const float* p = pS + gr * 2112 + n * 33;
            Ai += p[jj]; Af += p[8 + jj]; Ao += p[16 + jj]; Ag += p[24 + jj];
        }
        float ig = 1.0f / (1.0f + __expf(-Ai));
        float fg = 1.0f / (1.0f + __expf(-Af));
        float og = 1.0f / (1.0f + __expf(-Ao));
        float gg = tanhf(Ag);
        c_reg = fg * c_reg + ig * gg;
        float hv = og * tanhf(c_reg);

        out[((size_t)n * Ts + t) * Hh + j0 + jj] = hv;
        hTo[(j0 + jj) * 64 + n] = hv;

        __syncthreads();
        if (tid == 0) {
            __threadfence();
            atomicAdd(&g_barq[t][quarter], 1);
        }
    }
}

// ===================================================================
// Host launch
// ===================================================================
extern "C" void kernel_launch(void* const* d_in, const int* in_sizes, int n_in,
                              void* d_out, int out_size) {
    const float* x  = (const float*)d_in[0];   // (64, 512, 1024)
    const float* h0 = (const float*)d_in[1];   // (64, 1024)
    const float* Wx = (const float*)d_in[2];   // (1024, 4096)
    const float* Wh = (const float*)d_in[3];   // (1024, 4096)
    const float* b  = (const float*)d_in[4];   // (4096)
    float* out = (float*)d_out;                // (64, 512, 1024)

    cudaFuncSetAttribute(lstm_persist, cudaFuncAttributeMaxDynamicSharedMemorySize, 230400);
    cudaFuncSetAttribute(tc_gemm, cudaFuncAttributeMaxDynamicSharedMemorySize, 81920);

    prep<<<64, 256>>>(h0);
    conv_x<<<16384, 256>>>(x);
    conv_w<<<2048, 256>>>(Wx);

    dim3 gg(Gg / 128, (Nb * Ts) / 128);        // (32, 256) — N fastest for A L2 reuse
    tc_gemm<<<gg, 256, 81920>>>(b);

    lstm_persist<<<128, 512, 230400>>>(Wh, out);
}

// round 13
// speedup vs baseline: 3.8572x; 1.2222x over previous
#include <cuda_runtime.h>
#include <cuda_bf16.h>
#include <cstddef>
#include <cstdint>

#define Nb 64
#define Ts 512
#define Dd 1024
#define Hh 1024
#define Gg 4096   // 4*Hh

typedef unsigned long long u64;
typedef __nv_bfloat16 bf16;

// Scratch (static device arrays; no allocations).
__device__ float g_xw[(size_t)Nb * Ts * Gg];     // (t, n, 4H)
__device__ int   g_barq[Ts][4];                  // per-step, per-quarter barrier counters

// h state for the recurrence, bf16 hi/lo split, [n][k] layout, double-buffered.
__device__ __align__(16) bf16 g_hbh[2][Nb * Hh];
__device__ __align__(16) bf16 g_hbl[2][Nb * Hh];

// bf16-split operands for the tensor-core input GEMM.
__device__ __align__(16) bf16 g_Ah[(size_t)Nb * Ts * Dd];  // A hi [m][d], m=t*64+n
__device__ __align__(16) bf16 g_Al[(size_t)Nb * Ts * Dd];  // A lo
__device__ __align__(16) bf16 g_Bh[(size_t)Gg * Dd];       // Wx^T hi [g][d]
__device__ __align__(16) bf16 g_Bl[(size_t)Gg * Dd];       // Wx^T lo

union F2U { u64 u; float2 f; };

#define FFMA2(d, a, b) asm("fma.rn.f32x2 %0, %1, %2, %0;" : "+l"(d) : "l"(a), "l"(b))
#define PACK2(d, s)    asm("mov.b64 %0, {%1, %1};" : "=l"(d) : "r"(s))

__device__ __forceinline__ void cp16(void* smem, const void* g) {
    unsigned saddr = (unsigned)__cvta_generic_to_shared(smem);
    asm volatile("cp.async.cg.shared.global [%0], [%1], 16;" :: "r"(saddr), "l"(g));
}
#define CP_COMMIT() asm volatile("cp.async.commit_group;")
#define CP_WAIT1()  asm volatile("cp.async.wait_group 1;")
#define CP_WAIT0()  asm volatile("cp.async.wait_group 0;")

// mma.sync m16n8k16 row.col f32.bf16.bf16.f32 — baseline PTX (works on compute_103).
#define MMA16816(c, a0, a1, a2, a3, b0, b1) \
    asm volatile("mma.sync.aligned.m16n8k16.row.col.f32.bf16.bf16.f32 " \
                 "{%0,%1,%2,%3}, {%4,%5,%6,%7}, {%8,%9}, {%0,%1,%2,%3};" \
                 : "+f"((c)[0]), "+f"((c)[1]), "+f"((c)[2]), "+f"((c)[3]) \
                 : "r"(a0), "r"(a1), "r"(a2), "r"(a3), "r"(b0), "r"(b1))

// ===================================================================
// prep: zero barrier counters; convert h0 -> bf16 hi/lo [n][k]
// ===================================================================
__global__ void prep(const float* __restrict__ h0) {
    int tid = blockIdx.x * blockDim.x + threadIdx.x;
    int nt  = gridDim.x * blockDim.x;
    if (tid < Ts * 4) ((int*)g_barq)[tid] = 0;
    for (int i = tid; i < Nb * Hh; i += nt) {
        float v = h0[i];
        bf16 hh = __float2bfloat16(v);
        g_hbh[0][i] = hh;
        g_hbl[0][i] = __float2bfloat16(v - __bfloat162float(hh));
    }
}

// ===================================================================
// conv_x: x (N,T,D) fp32 -> bf16 hi/lo rows m = t*64+n.
// ===================================================================
__global__ void conv_x(const float* __restrict__ x) {
    size_t u = (size_t)blockIdx.x * blockDim.x + threadIdx.x;
    int m  = (int)(u >> 7);
    int d0 = (int)(u & 127) << 3;
    int t = m >> 6, n = m & 63;
    const float* src = x + ((size_t)n * Ts + t) * Dd + d0;
    float4 v0 = *(const float4*)src;
    float4 v1 = *(const float4*)(src + 4);
    float vv[8] = {v0.x, v0.y, v0.z, v0.w, v1.x, v1.y, v1.z, v1.w};
    union { bf16 b[8]; uint4 q; } H, L;
    #pragma unroll
    for (int j = 0; j < 8; j++) {
        bf16 h = __float2bfloat16(vv[j]);
        H.b[j] = h;
        L.b[j] = __float2bfloat16(vv[j] - __bfloat162float(h));
    }
    *(uint4*)(g_Ah + (size_t)m * Dd + d0) = H.q;
    *(uint4*)(g_Al + (size_t)m * Dd + d0) = L.q;
}

// ===================================================================
// conv_w: Wx [d][g] fp32 -> transposed bf16 hi/lo [g][d].
// ===================================================================
__global__ void conv_w(const float* __restrict__ Wx) {
    size_t u = (size_t)blockIdx.x * blockDim.x + threadIdx.x;
    int g  = (int)(u & 4095);
    int d0 = (int)(u >> 12) << 3;
    union { bf16 b[8]; uint4 q; } H, L;
    #pragma unroll
    for (int j = 0; j < 8; j++) {
        float v = Wx[(size_t)(d0 + j) * Gg + g];
        bf16 h = __float2bfloat16(v);
        H.b[j] = h;
        L.b[j] = __float2bfloat16(v - __bfloat162float(h));
    }
    *(uint4*)(g_Bh + (size_t)g * Dd + d0) = H.q;
    *(uint4*)(g_Bl + (size_t)g * Dd + d0) = L.q;
}

// ===================================================================
// tc_gemm: xW = A @ B^T + bias via mma.sync (UNCHANGED, passing R12).
// ===================================================================
typedef bf16 SmTile[128][40];

__global__ __launch_bounds__(256, 2) void tc_gemm(const float* __restrict__ bias) {
    extern __shared__ bf16 smraw[];
    SmTile* tiles = (SmTile*)smraw;

    const int tid = threadIdx.x;
    const int wid = tid >> 5;
    const int lid = tid & 31;
    const int grp = lid >> 2;
    const int tg  = lid & 3;
    const int wm  = wid >> 2;
    const int wn  = wid & 3;
    const int n0  = blockIdx.x * 128;
    const int m0  = blockIdx.y * 128;

    #define LOADTILES(buf, kt) do { \
        _Pragma("unroll") \
        for (int q = 0; q < 2; q++) { \
            int c  = tid * 2 + q; \
            int r  = c >> 2; \
            int kc = (c & 3) * 8; \
            size_t goff = (size_t)r * Dd + (kt) + kc; \
            cp16(&tiles[(buf)*4 + 0][r][kc], g_Ah + (size_t)m0 * Dd + goff); \
            cp16(&tiles[(buf)*4 + 1][r][kc], g_Al + (size_t)m0 * Dd + goff); \
            cp16(&tiles[(buf)*4 + 2][r][kc], g_Bh + (size_t)n0 * Dd + goff); \
            cp16(&tiles[(buf)*4 + 3][r][kc], g_Bl + (size_t)n0 * Dd + goff); \
        } \
    } while (0)

    float acc[4][4][4];
    #pragma unroll
    for (int mt = 0; mt < 4; mt++)
        #pragma unroll
        for (int nt = 0; nt < 4; nt++)
            #pragma unroll
            for (int e = 0; e < 4; e++) acc[mt][nt][e] = 0.0f;

    LOADTILES(0, 0);
    CP_COMMIT();

    int buf = 0;
    for (int kt = 0; kt < Dd; kt += 32) {
        if (kt + 32 < Dd) LOADTILES(buf ^ 1, kt + 32);
        CP_COMMIT();
        CP_WAIT1();
        __syncthreads();

        const SmTile& Ah_s = tiles[buf * 4 + 0];
        const SmTile& Al_s = tiles[buf * 4 + 1];
        const SmTile& Bh_s = tiles[buf * 4 + 2];
        const SmTile& Bl_s = tiles[buf * 4 + 3];

        #pragma unroll
        for (int ks = 0; ks < 32; ks += 16) {
            uint32_t af[4][4], bfr[4][2];
            const int k0 = ks + tg * 2;

            #pragma unroll
            for (int mt = 0; mt < 4; mt++) {
                int r = wm * 64 + mt * 16 + grp;
                af[mt][0] = *(const uint32_t*)&Ah_s[r][k0];
                af[mt][1] = *(const uint32_t*)&Ah_s[r + 8][k0];
                af[mt][2] = *(const uint32_t*)&Ah_s[r][k0 + 8];
                af[mt][3] = *(const uint32_t*)&Ah_s[r + 8][k0 + 8];
            }
            #pragma unroll
            for (int nt = 0; nt < 4; nt++) {
                int r = wn * 32 + nt * 8 + grp;
                bfr[nt][0] = *(const uint32_t*)&Bh_s[r][k0];
                bfr[nt][1] = *(const uint32_t*)&Bh_s[r][k0 + 8];
            }
            #pragma unroll
            for (int mt = 0; mt < 4; mt++)
                #pragma unroll
                for (int nt = 0; nt < 4; nt++)
                    MMA16816(acc[mt][nt], af[mt][0], af[mt][1], af[mt][2], af[mt][3],
                             bfr[nt][0], bfr[nt][1]);

            #pragma unroll
            for (int nt = 0; nt < 4; nt++) {
                int r = wn * 32 + nt * 8 + grp;
                bfr[nt][0] = *(const uint32_t*)&Bl_s[r][k0];
                bfr[nt][1] = *(const uint32_t*)&Bl_s[r][k0 + 8];
            }
            #pragma unroll
            for (int mt = 0; mt < 4; mt++)
                #pragma unroll
                for (int nt = 0; nt < 4; nt++)
                    MMA16816(acc[mt][nt], af[mt][0], af[mt][1], af[mt][2], af[mt][3],
                             bfr[nt][0], bfr[nt][1]);

            #pragma unroll
            for (int mt = 0; mt < 4; mt++) {
                int r = wm * 64 + mt * 16 + grp;
                af[mt][0] = *(const uint32_t*)&Al_s[r][k0];
                af[mt][1] = *(const uint32_t*)&Al_s[r + 8][k0];
                af[mt][2] = *(const uint32_t*)&Al_s[r][k0 + 8];
                af[mt][3] = *(const uint32_t*)&Al_s[r + 8][k0 + 8];
            }
            #pragma unroll
            for (int nt = 0; nt < 4; nt++) {
                int r = wn * 32 + nt * 8 + grp;
                bfr[nt][0] = *(const uint32_t*)&Bh_s[r][k0];
                bfr[nt][1] = *(const uint32_t*)&Bh_s[r][k0 + 8];
            }
            #pragma unroll
            for (int mt = 0; mt < 4; mt++)
                #pragma unroll
                for (int nt = 0; nt < 4; nt++)
                    MMA16816(acc[mt][nt], af[mt][0], af[mt][1], af[mt][2], af[mt][3],
                             bfr[nt][0], bfr[nt][1]);
        }
        __syncthreads();
        buf ^= 1;
    }

    #pragma unroll
    for (int mt = 0; mt < 4; mt++) {
        int mrow = m0 + wm * 64 + mt * 16 + grp;
        #pragma unroll
        for (int nt = 0; nt < 4; nt++) {
            int col = n0 + wn * 32 + nt * 8 + tg * 2;
            float2 bv = *(const float2*)(bias + col);
            float2 v0 = make_float2(acc[mt][nt][0] + bv.x, acc[mt][nt][1] + bv.y);
            float2 v1 = make_float2(acc[mt][nt][2] + bv.x, acc[mt][nt][3] + bv.y);
            *(float2*)(g_xw + (size_t)mrow * Gg + col) = v0;
            *(float2*)(g_xw + (size_t)(mrow + 8) * Gg + col) = v1;
        }
    }
    #undef LOADTILES
}

// ===================================================================
// Kernel 2: persistent LSTM recurrence — tensor-core version.
// Same skeleton as passing R10/R12 (quarter barriers, per-group named-bar
// chunk pipeline, dedicated partials, gate stage). GEMM is now bf16-split
// 3-term mma.sync: A = h [64 m][k] hi/lo (streamed, k16 chunks), B = Wh
// slice [32 cols][1032 k] hi/lo (smem-resident, converted once).
// Group g: K slice [256g, 256g+256), 16 chunks of k16. Warp wg in group
// owns m-tile rows 16wg..16wg+15, loops 4 n8 tiles over full local K.
// smem: Wh 132096 + h stages 49152 + partials 33792 = 215040 B.
// ===================================================================
#define WH_STRIDE 1032
#define HROW 24           // bf16 per staged h row (16 used + 8 pad); 48 B

__global__ __launch_bounds__(512, 1) void lstm_persist(const float* __restrict__ Wh,
                                                       float* __restrict__ out) {
    extern __shared__ char smc[];
    bf16*  Whh = (bf16*)smc;                          // [32][1032]
    bf16*  Whl = Whh + 32 * WH_STRIDE;                // [32][1032]
    char*  hSb = smc + 132096;                        // 4 groups x 2 bufs x 6144 B
    float* pS  = (float*)(smc + 181248);              // 4 groups x [64][33]

    const int tid = threadIdx.x;
    const int j0  = blockIdx.x * 8;
    const int quarter = blockIdx.x >> 5;
    const int g   = tid >> 7;               // K-split group 0..3
    const int tl  = tid & 127;
    const int wg  = tl >> 5;                // warp in group 0..3 -> m-tile
    const int lid = tid & 31;
    const int grp = lid >> 2;               // 0..7
    const int tg  = lid & 3;                // 0..3
    const int n   = tid >> 3;               // gate-stage row 0..63
    const int jj  = tid & 7;                // gate-stage col 0..7

    // ---- convert Wh slice -> smem bf16 hi/lo [c][k], c = gate*8+jj ----
    {
        int c  = tid & 31;
        int gate = c >> 3, cj = c & 7;
        const float* wp = Wh + (size_t)gate * Hh + j0 + cj;
        for (int k = tid >> 5; k < Hh; k += 16) {
            float w = wp[(size_t)k * Gg];
            bf16 wh = __float2bfloat16(w);
            Whh[c * WH_STRIDE + k] = wh;
            Whl[c * WH_STRIDE + k] = __float2bfloat16(w - __bfloat162float(wh));
        }
    }
    __syncthreads();

    float c_reg = 0.0f;
    const int kbase = g * 256;
    char* hg0 = hSb + g * 12288;            // buf 0 (6144 B: hi 3072 + lo 3072)
    char* hg1 = hg0 + 6144;                 // buf 1
    float* mypart = pS + g * 2112;

    const int ar = wg * 16 + grp;           // A-frag row within [64]

    for (int t = 0; t < Ts; t++) {
        const bf16* hbh = g_hbh[t & 1];
        const bf16* hbl = g_hbl[t & 1];
        bf16* hoh = g_hbh[(t + 1) & 1];
        bf16* hol = g_hbl[(t + 1) & 1];

        // prefetch xW addends (DRAM latency overlaps the spin below)
        const float* xwp = g_xw + ((size_t)t * Nb + n) * Gg + j0 + jj;
        float xi = xwp[0], xf = xwp[Hh], xo = xwp[2 * Hh], xg = xwp[3 * Hh];

        // per-group input-ready wait: quarter g published step-t input
        if (t > 0) {
            if (tl == 0) {
                int v;
                do {
                    asm volatile("ld.acquire.gpu.global.b32 %0, [%1];"
                                 : "=r"(v) : "l"(&g_barq[t - 1][g]) : "memory");
                } while (v < 32);
            }
            asm volatile("bar.sync %0, 128;" :: "r"(g + 1) : "memory");
        }

        float acc[4][4];
        #pragma unroll
        for (int nt = 0; nt < 4; nt++)
            #pragma unroll
            for (int e = 0; e < 4; e++) acc[nt][e] = 0.0f;

        // stage loader: 2 jobs/thread/chunk. job j (0..255): half=j>>7,
        // r=(j&127)>>1, seg=j&1 -> 16B from [n=r][k 8*seg..] of hi or lo.
        #define LOADCHUNK(dst, ch) do { \
            _Pragma("unroll") \
            for (int q = 0; q < 2; q++) { \
                int j2 = tl + q * 128; \
                int half = j2 >> 7; /* q==0 -> hi, q==1 -> lo (tl<128) */ \
                int r = (j2 & 127) >> 1; \
                int seg = j2 & 1; \
                const bf16* srcb = (half ? hbl : hbh) + (size_t)r * Hh + kbase + (ch) * 16 + seg * 8; \
                cp16((dst) + half * 3072 + r * 48 + seg * 16, srcb); \
            } \
        } while (0)

        LOADCHUNK(hg0, 0);
        CP_COMMIT();

        #pragma unroll 1
        for (int ch = 0; ch < 16; ch++) {
            char* cur = (ch & 1) ? hg1 : hg0;
            char* nxt = (ch & 1) ? hg0 : hg1;
            if (ch < 15) LOADCHUNK(nxt, ch + 1);
            CP_COMMIT();
            CP_WAIT1();
            asm volatile("bar.sync %0, 128;" :: "r"(g + 1) : "memory"); // chunk landed

            const bf16* Ah = (const bf16*)cur;          // [64][24]
            const bf16* Al = Ah + 1536;
            const int kk = kbase + ch * 16 + tg * 2;    // B k index

            uint32_t ah0 = *(const uint32_t*)&Ah[ar * HROW + tg * 2];
            uint32_t ah1 = *(const uint32_t*)&Ah[(ar + 8) * HROW + tg * 2];
            uint32_t ah2 = *(const uint32_t*)&Ah[ar * HROW + tg * 2 + 8];
            uint32_t ah3 = *(const uint32_t*)&Ah[(ar + 8) * HROW + tg * 2 + 8];
            uint32_t al0 = *(const uint32_t*)&Al[ar * HROW + tg * 2];
            uint32_t al1 = *(const uint32_t*)&Al[(ar + 8) * HROW + tg * 2];
            uint32_t al2 = *(const uint32_t*)&Al[ar * HROW + tg * 2 + 8];
            uint32_t al3 = *(const uint32_t*)&Al[(ar + 8) * HROW + tg * 2 + 8];

            #pragma unroll
            for (int nt = 0; nt < 4; nt++) {
                int br = nt * 8 + grp;
                uint32_t bh0 = *(const uint32_t*)&Whh[br * WH_STRIDE + kk];
                uint32_t bh1 = *(const uint32_t*)&Whh[br * WH_STRIDE + kk + 8];
                uint32_t bl0 = *(const uint32_t*)&Whl[br * WH_STRIDE + kk];
                uint32_t bl1 = *(const uint32_t*)&Whl[br * WH_STRIDE + kk + 8];
                MMA16816(acc[nt], ah0, ah1, ah2, ah3, bh0, bh1);
                MMA16816(acc[nt], ah0, ah1, ah2, ah3, bl0, bl1);
                MMA16816(acc[nt], al0, al1, al2, al3, bh0, bh1);
            }
            asm volatile("bar.sync %0, 128;" :: "r"(g + 1) : "memory"); // cur free
        }
        #undef LOADCHUNK

        // write K-split partials to the DEDICATED region ([64][33])
        #pragma unroll
        for (int nt = 0; nt < 4; nt++) {
            int col = nt * 8 + tg * 2;
            float* p0 = mypart + ar * 33 + col;
            p0[0] = acc[nt][0]; p0[1] = acc[nt][1];
            float* p1 = mypart + (ar + 8) * 33 + col;
            p1[0] = acc[nt][2]; p1[1] = acc[nt][3];
        }
        __syncthreads();   // all groups' partials visible; orders spins before h writes

        // gates: reduce 4 partials + xW, update c (register), emit h
        float Ai = xi, Af = xf, Ao = xo, Ag = xg;
        #pragma unroll
        for (int gr = 0; gr < 4; gr++) {
            const float* p = pS + gr * 2112 + n * 33;
            Ai += p[jj]; Af += p[8 + jj]; Ao += p[16 + jj]; Ag += p[24 + jj];
        }
        float ig = 1.0f / (1.0f + __expf(-Ai));
        float fg = 1.0f / (1.0f + __expf(-Af));
        float og = 1.0f / (1.0f + __expf(-Ao));
        float gg = tanhf(Ag);
        c_reg = fg * c_reg + ig * gg;
        float hv = og * tanhf(c_reg);

        out[((size_t)n * Ts + t) * Hh + j0 + jj] = hv;
        bf16 hh = __float2bfloat16(hv);
        hoh[n * Hh + j0 + jj] = hh;
        hol[n * Hh + j0 + jj] = __float2bfloat16(hv - __bfloat162float(hh));

        // publish: this CTA's h columns for step t+1 are ready
        __syncthreads();
        if (tid == 0) {
            __threadfence();
            atomicAdd(&g_barq[t][quarter], 1);
        }
    }
}

// ===================================================================
// Host launch
// ===================================================================
extern "C" void kernel_launch(void* const* d_in, const int* in_sizes, int n_in,
                              void* d_out, int out_size) {
    const float* x  = (const float*)d_in[0];   // (64, 512, 1024)
    const float* h0 = (const float*)d_in[1];   // (64, 1024)
    const float* Wx = (const float*)d_in[2];   // (1024, 4096)
    const float* Wh = (const float*)d_in[3];   // (1024, 4096)
    const float* b  = (const float*)d_in[4];   // (4096)
    float* out = (float*)d_out;                // (64, 512, 1024)

    cudaFuncSetAttribute(lstm_persist, cudaFuncAttributeMaxDynamicSharedMemorySize, 215040);
    cudaFuncSetAttribute(tc_gemm, cudaFuncAttributeMaxDynamicSharedMemorySize, 81920);

    prep<<<64, 256>>>(h0);
    conv_x<<<16384, 256>>>(x);
    conv_w<<<2048, 256>>>(Wx);

    dim3 gg(Gg / 128, (Nb * Ts) / 128);        // (32, 256) — N fastest for A L2 reuse
    tc_gemm<<<gg, 256, 81920>>>(b);

    lstm_persist<<<128, 512, 215040>>>(Wh, out);
}

// round 14
// speedup vs baseline: 4.0443x; 1.0485x over previous
#include <cuda_runtime.h>
#include <cuda_bf16.h>
#include <cstddef>
#include <cstdint>

#define Nb 64
#define Ts 512
#define Dd 1024
#define Hh 1024
#define Gg 4096   // 4*Hh

typedef unsigned long long u64;
typedef __nv_bfloat16 bf16;

// Scratch (static device arrays; no allocations).
__device__ float g_xw[(size_t)Nb * Ts * Gg];     // (t, n, 4H)
__device__ int   g_barq[Ts][4];                  // per-step, per-quarter barrier counters

// h state for the recurrence, bf16 hi/lo split, [n][k] layout, double-buffered.
__device__ __align__(16) bf16 g_hbh[2][Nb * Hh];
__device__ __align__(16) bf16 g_hbl[2][Nb * Hh];

// bf16-split operands for the tensor-core input GEMM.
__device__ __align__(16) bf16 g_Ah[(size_t)Nb * Ts * Dd];  // A hi [m][d], m=t*64+n
__device__ __align__(16) bf16 g_Al[(size_t)Nb * Ts * Dd];  // A lo
__device__ __align__(16) bf16 g_Bh[(size_t)Gg * Dd];       // Wx^T hi [g][d]
__device__ __align__(16) bf16 g_Bl[(size_t)Gg * Dd];       // Wx^T lo

__device__ __forceinline__ void cp16(void* smem, const void* g) {
    unsigned saddr = (unsigned)__cvta_generic_to_shared(smem);
    asm volatile("cp.async.cg.shared.global [%0], [%1], 16;" :: "r"(saddr), "l"(g));
}
#define CP_COMMIT() asm volatile("cp.async.commit_group;")
#define CP_WAIT1()  asm volatile("cp.async.wait_group 1;")
#define CP_WAIT2()  asm volatile("cp.async.wait_group 2;")

// mma.sync m16n8k16 row.col f32.bf16.bf16.f32 — baseline PTX (works on compute_103).
#define MMA16816(c, a0, a1, a2, a3, b0, b1) \
    asm volatile("mma.sync.aligned.m16n8k16.row.col.f32.bf16.bf16.f32 " \
                 "{%0,%1,%2,%3}, {%4,%5,%6,%7}, {%8,%9}, {%0,%1,%2,%3};" \
                 : "+f"((c)[0]), "+f"((c)[1]), "+f"((c)[2]), "+f"((c)[3]) \
                 : "r"(a0), "r"(a1), "r"(a2), "r"(a3), "r"(b0), "r"(b1))

// ===================================================================
// prep: zero barrier counters; convert h0 -> bf16 hi/lo [n][k]
// ===================================================================
__global__ void prep(const float* __restrict__ h0) {
    int tid = blockIdx.x * blockDim.x + threadIdx.x;
    int nt  = gridDim.x * blockDim.x;
    if (tid < Ts * 4) ((int*)g_barq)[tid] = 0;
    for (int i = tid; i < Nb * Hh; i += nt) {
        float v = h0[i];
        bf16 hh = __float2bfloat16(v);
        g_hbh[0][i] = hh;
        g_hbl[0][i] = __float2bfloat16(v - __bfloat162float(hh));
    }
}

// ===================================================================
// conv_x: x (N,T,D) fp32 -> bf16 hi/lo rows m = t*64+n.
// ===================================================================
__global__ void conv_x(const float* __restrict__ x) {
    size_t u = (size_t)blockIdx.x * blockDim.x + threadIdx.x;
    int m  = (int)(u >> 7);
    int d0 = (int)(u & 127) << 3;
    int t = m >> 6, n = m & 63;
    const float* src = x + ((size_t)n * Ts + t) * Dd + d0;
    float4 v0 = *(const float4*)src;
    float4 v1 = *(const float4*)(src + 4);
    float vv[8] = {v0.x, v0.y, v0.z, v0.w, v1.x, v1.y, v1.z, v1.w};
    union { bf16 b[8]; uint4 q; } H, L;
    #pragma unroll
    for (int j = 0; j < 8; j++) {
        bf16 h = __float2bfloat16(vv[j]);
        H.b[j] = h;
        L.b[j] = __float2bfloat16(vv[j] - __bfloat162float(h));
    }
    *(uint4*)(g_Ah + (size_t)m * Dd + d0) = H.q;
    *(uint4*)(g_Al + (size_t)m * Dd + d0) = L.q;
}

// ===================================================================
// conv_w: Wx [d][g] fp32 -> transposed bf16 hi/lo [g][d].
// ===================================================================
__global__ void conv_w(const float* __restrict__ Wx) {
    size_t u = (size_t)blockIdx.x * blockDim.x + threadIdx.x;
    int g  = (int)(u & 4095);
    int d0 = (int)(u >> 12) << 3;
    union { bf16 b[8]; uint4 q; } H, L;
    #pragma unroll
    for (int j = 0; j < 8; j++) {
        float v = Wx[(size_t)(d0 + j) * Gg + g];
        bf16 h = __float2bfloat16(v);
        H.b[j] = h;
        L.b[j] = __float2bfloat16(v - __bfloat162float(h));
    }
    *(uint4*)(g_Bh + (size_t)g * Dd + d0) = H.q;
    *(uint4*)(g_Bl + (size_t)g * Dd + d0) = L.q;
}

// ===================================================================
// tc_gemm: xW = A @ B^T + bias via mma.sync (UNCHANGED, passing R12/R13).
// ===================================================================
typedef bf16 SmTile[128][40];

__global__ __launch_bounds__(256, 2) void tc_gemm(const float* __restrict__ bias) {
    extern __shared__ bf16 smraw[];
    SmTile* tiles = (SmTile*)smraw;

    const int tid = threadIdx.x;
    const int wid = tid >> 5;
    const int lid = tid & 31;
    const int grp = lid >> 2;
    const int tg  = lid & 3;
    const int wm  = wid >> 2;
    const int wn  = wid & 3;
    const int n0  = blockIdx.x * 128;
    const int m0  = blockIdx.y * 128;

    #define LOADTILES(buf, kt) do { \
        _Pragma("unroll") \
        for (int q = 0; q < 2; q++) { \
            int c  = tid * 2 + q; \
            int r  = c >> 2; \
            int kc = (c & 3) * 8; \
            size_t goff = (size_t)r * Dd + (kt) + kc; \
            cp16(&tiles[(buf)*4 + 0][r][kc], g_Ah + (size_t)m0 * Dd + goff); \
            cp16(&tiles[(buf)*4 + 1][r][kc], g_Al + (size_t)m0 * Dd + goff); \
            cp16(&tiles[(buf)*4 + 2][r][kc], g_Bh + (size_t)n0 * Dd + goff); \
            cp16(&tiles[(buf)*4 + 3][r][kc], g_Bl + (size_t)n0 * Dd + goff); \
        } \
    } while (0)

    float acc[4][4][4];
    #pragma unroll
    for (int mt = 0; mt < 4; mt++)
        #pragma unroll
        for (int nt = 0; nt < 4; nt++)
            #pragma unroll
            for (int e = 0; e < 4; e++) acc[mt][nt][e] = 0.0f;

    LOADTILES(0, 0);
    CP_COMMIT();

    int buf = 0;
    for (int kt = 0; kt < Dd; kt += 32) {
        if (kt + 32 < Dd) LOADTILES(buf ^ 1, kt + 32);
        CP_COMMIT();
        CP_WAIT1();
        __syncthreads();

        const SmTile& Ah_s = tiles[buf * 4 + 0];
        const SmTile& Al_s = tiles[buf * 4 + 1];
        const SmTile& Bh_s = tiles[buf * 4 + 2];
        const SmTile& Bl_s = tiles[buf * 4 + 3];

        #pragma unroll
        for (int ks = 0; ks < 32; ks += 16) {
            uint32_t af[4][4], bfr[4][2];
            const int k0 = ks + tg * 2;

            #pragma unroll
            for (int mt = 0; mt < 4; mt++) {
                int r = wm * 64 + mt * 16 + grp;
                af[mt][0] = *(const uint32_t*)&Ah_s[r][k0];
                af[mt][1] = *(const uint32_t*)&Ah_s[r + 8][k0];
                af[mt][2] = *(const uint32_t*)&Ah_s[r][k0 + 8];
                af[mt][3] = *(const uint32_t*)&Ah_s[r + 8][k0 + 8];
            }
            #pragma unroll
            for (int nt = 0; nt < 4; nt++) {
                int r = wn * 32 + nt * 8 + grp;
                bfr[nt][0] = *(const uint32_t*)&Bh_s[r][k0];
                bfr[nt][1] = *(const uint32_t*)&Bh_s[r][k0 + 8];
            }
            #pragma unroll
            for (int mt = 0; mt < 4; mt++)
                #pragma unroll
                for (int nt = 0; nt < 4; nt++)
                    MMA16816(acc[mt][nt], af[mt][0], af[mt][1], af[mt][2], af[mt][3],
                             bfr[nt][0], bfr[nt][1]);

            #pragma unroll
            for (int nt = 0; nt < 4; nt++) {
                int r = wn * 32 + nt * 8 + grp;
                bfr[nt][0] = *(const uint32_t*)&Bl_s[r][k0];
                bfr[nt][1] = *(const uint32_t*)&Bl_s[r][k0 + 8];
            }
            #pragma unroll
            for (int mt = 0; mt < 4; mt++)
                #pragma unroll
                for (int nt = 0; nt < 4; nt++)
                    MMA16816(acc[mt][nt], af[mt][0], af[mt][1], af[mt][2], af[mt][3],
                             bfr[nt][0], bfr[nt][1]);

            #pragma unroll
            for (int mt = 0; mt < 4; mt++) {
                int r = wm * 64 + mt * 16 + grp;
                af[mt][0] = *(const uint32_t*)&Al_s[r][k0];
                af[mt][1] = *(const uint32_t*)&Al_s[r + 8][k0];
                af[mt][2] = *(const uint32_t*)&Al_s[r][k0 + 8];
                af[mt][3] = *(const uint32_t*)&Al_s[r + 8][k0 + 8];
            }
            #pragma unroll
            for (int nt = 0; nt < 4; nt++) {
                int r = wn * 32 + nt * 8 + grp;
                bfr[nt][0] = *(const uint32_t*)&Bh_s[r][k0];
                bfr[nt][1] = *(const uint32_t*)&Bh_s[r][k0 + 8];
            }
            #pragma unroll
            for (int mt = 0; mt < 4; mt++)
                #pragma unroll
                for (int nt = 0; nt < 4; nt++)
                    MMA16816(acc[mt][nt], af[mt][0], af[mt][1], af[mt][2], af[mt][3],
                             bfr[nt][0], bfr[nt][1]);
        }
        __syncthreads();
        buf ^= 1;
    }

    #pragma unroll
    for (int mt = 0; mt < 4; mt++) {
        int mrow = m0 + wm * 64 + mt * 16 + grp;
        #pragma unroll
        for (int nt = 0; nt < 4; nt++) {
            int col = n0 + wn * 32 + nt * 8 + tg * 2;
            float2 bv = *(const float2*)(bias + col);
            float2 v0 = make_float2(acc[mt][nt][0] + bv.x, acc[mt][nt][1] + bv.y);
            float2 v1 = make_float2(acc[mt][nt][2] + bv.x, acc[mt][nt][3] + bv.y);
            *(float2*)(g_xw + (size_t)mrow * Gg + col) = v0;
            *(float2*)(g_xw + (size_t)(mrow + 8) * Gg + col) = v1;
        }
    }
    #undef LOADTILES
}

// ===================================================================
// Kernel 2: persistent LSTM recurrence — tensor-core, deep pipeline.
// Changes vs passing R13:
//  * 4 stage buffers per group, wait_group 2, ONE named bar per chunk
//    (depth-3 prefetch hides L2 latency; 16 bars/step instead of 32).
//    Per iter: wait<=2 (chunk ch landed) -> bar (readers of the write
//    target buf[(ch-1)&3] are all done) -> issue ch+3 -> commit ->
//    compute buf[ch&3]. Tail iters commit empty groups to keep counts.
//  * Partials region ALIASED into each group's stage bufs 0-1 (free
//    after the chunk loop; gate reads end before the publish sync,
//    next-step loads start after it in every thread).
// smem: Wh 132096 + stages 98304 = 230400 B (same footprint as R9/R10).
// ===================================================================
#define WH_STRIDE 1032
#define HROW 24           // bf16 per staged h row (16 used + 8 pad); 48 B
#define GSTG 24576        // per-group stage region: 4 bufs x 6144 B

__global__ __launch_bounds__(512, 1) void lstm_persist(const float* __restrict__ Wh,
                                                       float* __restrict__ out) {
    extern __shared__ char smc[];
    bf16*  Whh = (bf16*)smc;                          // [32][1032]
    bf16*  Whl = Whh + 32 * WH_STRIDE;                // [32][1032]
    char*  hSb = smc + 132096;                        // 4 groups x 4 bufs x 6144 B

    const int tid = threadIdx.x;
    const int j0  = blockIdx.x * 8;
    const int quarter = blockIdx.x >> 5;
    const int g   = tid >> 7;               // K-split group 0..3
    const int tl  = tid & 127;
    const int wg  = tl >> 5;                // warp in group 0..3 -> m-tile
    const int lid = tid & 31;
    const int grp = lid >> 2;               // 0..7
    const int tg  = lid & 3;                // 0..3
    const int n   = tid >> 3;               // gate-stage row 0..63
    const int jj  = tid & 7;                // gate-stage col 0..7

    // ---- convert Wh slice -> smem bf16 hi/lo [c][k], c = gate*8+jj ----
    {
        int c  = tid & 31;
        int gate = c >> 3, cj = c & 7;
        const float* wp = Wh + (size_t)gate * Hh + j0 + cj;
        for (int k = tid >> 5; k < Hh; k += 16) {
            float w = wp[(size_t)k * Gg];
            bf16 wh = __float2bfloat16(w);
            Whh[c * WH_STRIDE + k] = wh;
            Whl[c * WH_STRIDE + k] = __float2bfloat16(w - __bfloat162float(wh));
        }
    }
    __syncthreads();

    float c_reg = 0.0f;
    const int kbase = g * 256;
    char*  hg     = hSb + g * GSTG;          // 4 stage bufs, 6144 B each
    float* mypart = (float*)hg;              // partials alias bufs 0-1 (8448 B)

    const int ar = wg * 16 + grp;            // A-frag row within [64]

    for (int t = 0; t < Ts; t++) {
        const bf16* hbh = g_hbh[t & 1];
        const bf16* hbl = g_hbl[t & 1];
        bf16* hoh = g_hbh[(t + 1) & 1];
        bf16* hol = g_hbl[(t + 1) & 1];

        // prefetch xW addends (DRAM latency overlaps the spin below)
        const float* xwp = g_xw + ((size_t)t * Nb + n) * Gg + j0 + jj;
        float xi = xwp[0], xf = xwp[Hh], xo = xwp[2 * Hh], xg = xwp[3 * Hh];

        // per-group input-ready wait: quarter g published step-t input
        if (t > 0) {
            if (tl == 0) {
                int v;
                do {
                    asm volatile("ld.acquire.gpu.global.b32 %0, [%1];"
                                 : "=r"(v) : "l"(&g_barq[t - 1][g]) : "memory");
                } while (v < 32);
            }
            asm volatile("bar.sync %0, 128;" :: "r"(g + 1) : "memory");
        }

        float acc[4][4];
        #pragma unroll
        for (int nt = 0; nt < 4; nt++)
            #pragma unroll
            for (int e = 0; e < 4; e++) acc[nt][e] = 0.0f;

        // stage loader: 2 jobs/thread/chunk. job j (0..255): half=j>>7,
        // r=(j&127)>>1, seg=j&1 -> 16B from [n=r][k 8*seg..] of hi or lo.
        #define LOADCHUNK(dst, ch) do { \
            _Pragma("unroll") \
            for (int q = 0; q < 2; q++) { \
                int j2 = tl + q * 128; \
                int half = j2 >> 7; \
                int r = (j2 & 127) >> 1; \
                int seg = j2 & 1; \
                const bf16* srcb = (half ? hbl : hbh) + (size_t)r * Hh + kbase + (ch) * 16 + seg * 8; \
                cp16((dst) + half * 3072 + r * 48 + seg * 16, srcb); \
            } \
        } while (0)

        // prologue: chunks 0,1,2 into bufs 0,1,2 (3 committed groups)
        LOADCHUNK(hg + 0 * 6144, 0); CP_COMMIT();
        LOADCHUNK(hg + 1 * 6144, 1); CP_COMMIT();
        LOADCHUNK(hg + 2 * 6144, 2); CP_COMMIT();

        #pragma unroll 1
        for (int ch = 0; ch < 16; ch++) {
            CP_WAIT2();                                               // chunk ch landed
            asm volatile("bar.sync %0, 128;" :: "r"(g + 1) : "memory"); // readers of
                                                                        // buf[(ch-1)&3] done
            if (ch < 13) LOADCHUNK(hg + ((ch + 3) & 3) * 6144, ch + 3);
            CP_COMMIT();

            const bf16* Ah = (const bf16*)(hg + (ch & 3) * 6144);     // [64][24]
            const bf16* Al = Ah + 1536;
            const int kk = kbase + ch * 16 + tg * 2;                  // B k index

            uint32_t ah0 = *(const uint32_t*)&Ah[ar * HROW + tg * 2];
            uint32_t ah1 = *(const uint32_t*)&Ah[(ar + 8) * HROW + tg * 2];
            uint32_t ah2 = *(const uint32_t*)&Ah[ar * HROW + tg * 2 + 8];
            uint32_t ah3 = *(const uint32_t*)&Ah[(ar + 8) * HROW + tg * 2 + 8];
            uint32_t al0 = *(const uint32_t*)&Al[ar * HROW + tg * 2];
            uint32_t al1 = *(const uint32_t*)&Al[(ar + 8) * HROW + tg * 2];
            uint32_t al2 = *(const uint32_t*)&Al[ar * HROW + tg * 2 + 8];
            uint32_t al3 = *(const uint32_t*)&Al[(ar + 8) * HROW + tg * 2 + 8];

            #pragma unroll
            for (int nt = 0; nt < 4; nt++) {
                int br = nt * 8 + grp;
                uint32_t bh0 = *(const uint32_t*)&Whh[br * WH_STRIDE + kk];
                uint32_t bh1 = *(const uint32_t*)&Whh[br * WH_STRIDE + kk + 8];
                uint32_t bl0 = *(const uint32_t*)&Whl[br * WH_STRIDE + kk];
                uint32_t bl1 = *(const uint32_t*)&Whl[br * WH_STRIDE + kk + 8];
                MMA16816(acc[nt], ah0, ah1, ah2, ah3, bh0, bh1);
                MMA16816(acc[nt], ah0, ah1, ah2, ah3, bl0, bl1);
                MMA16816(acc[nt], al0, al1, al2, al3, bh0, bh1);
            }
        }
        #undef LOADCHUNK

        // write K-split partials into this group's stage bufs 0-1 ([64][33]).
        // Safe: bars guaranteed chunks<=14 compute done; ch15 read buf3 only.
        #pragma unroll
        for (int nt = 0; nt < 4; nt++) {
            int col = nt * 8 + tg * 2;
            float* p0 = mypart + ar * 33 + col;
            p0[0] = acc[nt][0]; p0[1] = acc[nt][1];
            float* p1 = mypart + (ar + 8) * 33 + col;
            p1[0] = acc[nt][2]; p1[1] = acc[nt][3];
        }
        __syncthreads();   // all groups' partials visible; orders spins before h writes

        // gates: reduce 4 partials + xW, update c (register), emit h
        float Ai = xi, Af = xf, Ao = xo, Ag = xg;
        #pragma unroll
        for (int gr = 0; gr < 4; gr++) {
            const float* p = (const float*)(hSb + gr * GSTG) + n * 33;
            Ai += p[jj]; Af += p[8 + jj]; Ao += p[16 + jj]; Ag += p[24 + jj];
        }
        float ig = 1.0f / (1.0f + __expf(-Ai));
        float fg = 1.0f / (1.0f + __expf(-Af));
        float og = 1.0f / (1.0f + __expf(-Ao));
        float gg = tanhf(Ag);
        c_reg = fg * c_reg + ig * gg;
        float hv = og * tanhf(c_reg);

        out[((size_t)n * Ts + t) * Hh + j0 + jj] = hv;
        bf16 hh = __float2bfloat16(hv);
        hoh[n * Hh + j0 + jj] = hh;
        hol[n * Hh + j0 + jj] = __float2bfloat16(hv - __bfloat162float(hh));

        // publish: this CTA's h columns for step t+1 are ready.
        // (gate reads of aliased partials completed before this sync;
        //  next step's stage loads start after it in every thread)
        __syncthreads();
        if (tid == 0) {
            __threadfence();
            atomicAdd(&g_barq[t][quarter], 1);
        }
    }
}

// ===================================================================
// Host launch
// ===================================================================
extern "C" void kernel_launch(void* const* d_in, const int* in_sizes, int n_in,
                              void* d_out, int out_size) {
    const float* x  = (const float*)d_in[0];   // (64, 512, 1024)
    const float* h0 = (const float*)d_in[1];   // (64, 1024)
    const float* Wx = (const float*)d_in[2];   // (1024, 4096)
    const float* Wh = (const float*)d_in[3];   // (1024, 4096)
    const float* b  = (const float*)d_in[4];   // (4096)
    float* out = (float*)d_out;                // (64, 512, 1024)

    cudaFuncSetAttribute(lstm_persist, cudaFuncAttributeMaxDynamicSharedMemorySize, 230400);
    cudaFuncSetAttribute(tc_gemm, cudaFuncAttributeMaxDynamicSharedMemorySize, 81920);

    prep<<<64, 256>>>(h0);
    conv_x<<<16384, 256>>>(x);
    conv_w<<<2048, 256>>>(Wx);

    dim3 gg(Gg / 128, (Nb * Ts) / 128);        // (32, 256) — N fastest for A L2 reuse
    tc_gemm<<<gg, 256, 81920>>>(b);

    lstm_persist<<<128, 512, 230400>>>(Wh, out);
}